// round 1
// baseline (speedup 1.0000x reference)
#include <cuda_runtime.h>
#include <cstdint>

#define B      64
#define PP     196
#define ENC    2048
#define LCAP   32
#define V      20000
#define ATT    512
#define EMB    512
#define DEC    512
#define TSTEPS 31
#define XDIM   (EMB+ENC)   /* 2560 */
#define G4     (4*DEC)     /* 2048 */

// ---------------- device scratch (static globals: no runtime allocation) ----------------
__device__ float g_att1[(size_t)B*PP*ATT];   // [B*P, ATT] encoder attention half (+bias)
__device__ float g_mean[B*ENC];
__device__ float g_h[B*DEC];
__device__ float g_c[B*DEC];
__device__ float g_att2[B*ATT];              // h @ W_dec_att^T (no bias yet)
__device__ float g_gatepre[B*ENC];           // h @ W_beta^T (no bias yet)
__device__ float g_gates[B*G4];              // h @ W_hh^T (then + x@W_ih^T partials)
__device__ float g_gpart[4*(size_t)B*G4];    // split-K partials of x @ W_ih^T
__device__ float g_x[B*XDIM];                // [emb | gate*awe]
__device__ int   g_bact[TSTEPS];             // active batch prefix per step

__device__ __forceinline__ float sigmoidf_(float x){ return 1.0f/(1.0f+expf(-x)); }

// ---------------- one-time kernels ----------------
__global__ void k_bact(const int* __restrict__ caplen){
  int t = threadIdx.x;
  if (t < TSTEPS){
    int c = 0;
    for (int b=0;b<B;b++) c += ((caplen[b]-1) > t) ? 1 : 0;
    g_bact[t] = c;
  }
}

__global__ void k_mean(const float* __restrict__ enc){
  int b = blockIdx.x;
  int e = blockIdx.y*256 + threadIdx.x;
  const float* p0 = enc + (size_t)b*PP*ENC + e;
  float s = 0.f;
  #pragma unroll 4
  for (int p=0;p<PP;p++) s += p0[(size_t)p*ENC];
  g_mean[b*ENC + e] = s * (1.0f/PP);
}

// h0/c0: [64,1024] = mean @ [W_init_h ; W_init_c]^T + bias.  BM=64 BN=32 BK=32.
__global__ void k_init_hc(const float* __restrict__ Wh, const float* __restrict__ bh,
                          const float* __restrict__ Wc, const float* __restrict__ bc){
  __shared__ float sA[32][68];
  __shared__ float sW[32][34];
  int tid = threadIdx.x;
  int tx = tid & 15, ty = tid >> 4;
  int gn0 = blockIdx.x * 32;
  const float* Wp = (gn0 < DEC) ? (Wh + (size_t)gn0*ENC) : (Wc + (size_t)(gn0-DEC)*ENC);
  float acc[4][2] = {};
  for (int k0=0; k0<ENC; k0+=32){
    #pragma unroll
    for (int i=0;i<2;i++){
      int lin = tid + i*256;
      int row = lin >> 3, kq = lin & 7;
      float4 v = *(const float4*)(g_mean + row*ENC + k0 + kq*4);
      sA[kq*4+0][row]=v.x; sA[kq*4+1][row]=v.y; sA[kq*4+2][row]=v.z; sA[kq*4+3][row]=v.w;
    }
    {
      int n = tid >> 3, kq = tid & 7;
      float4 v = *(const float4*)(Wp + (size_t)n*ENC + k0 + kq*4);
      sW[kq*4+0][n]=v.x; sW[kq*4+1][n]=v.y; sW[kq*4+2][n]=v.z; sW[kq*4+3][n]=v.w;
    }
    __syncthreads();
    #pragma unroll
    for (int k=0;k<32;k++){
      float4 a = *(const float4*)&sA[k][ty*4];
      float2 w = *(const float2*)&sW[k][tx*2];
      acc[0][0] += a.x*w.x; acc[0][1] += a.x*w.y;
      acc[1][0] += a.y*w.x; acc[1][1] += a.y*w.y;
      acc[2][0] += a.z*w.x; acc[2][1] += a.z*w.y;
      acc[3][0] += a.w*w.x; acc[3][1] += a.w*w.y;
    }
    __syncthreads();
  }
  #pragma unroll
  for (int i=0;i<4;i++){
    int m = ty*4+i;
    #pragma unroll
    for (int j=0;j<2;j++){
      int gn = gn0 + tx*2 + j;
      if (gn < DEC) g_h[m*DEC + gn]       = acc[i][j] + bh[gn];
      else          g_c[m*DEC + (gn-DEC)] = acc[i][j] + bc[gn-DEC];
    }
  }
}

// att1 = encoder_out @ W_enc_att^T + b_enc_att.  M=12544 N=512 K=2048. BM=BN=64 BK=16.
__global__ void k_att1(const float* __restrict__ A, const float* __restrict__ W,
                       const float* __restrict__ bias){
  __shared__ float sA[16][68];
  __shared__ float sW[16][68];
  int tid=threadIdx.x, tx=tid&15, ty=tid>>4;
  int m0 = blockIdx.y*64, gn0 = blockIdx.x*64;
  float acc[4][4] = {};
  for (int k0=0;k0<ENC;k0+=16){
    {
      int row=tid>>2, kq=tid&3;
      float4 v = *(const float4*)(A + (size_t)(m0+row)*ENC + k0 + kq*4);
      sA[kq*4+0][row]=v.x; sA[kq*4+1][row]=v.y; sA[kq*4+2][row]=v.z; sA[kq*4+3][row]=v.w;
    }
    {
      int n=tid>>2, kq=tid&3;
      float4 v = *(const float4*)(W + (size_t)(gn0+n)*ENC + k0 + kq*4);
      sW[kq*4+0][n]=v.x; sW[kq*4+1][n]=v.y; sW[kq*4+2][n]=v.z; sW[kq*4+3][n]=v.w;
    }
    __syncthreads();
    #pragma unroll
    for (int k=0;k<16;k++){
      float4 a=*(const float4*)&sA[k][ty*4];
      float4 w=*(const float4*)&sW[k][tx*4];
      acc[0][0]+=a.x*w.x; acc[0][1]+=a.x*w.y; acc[0][2]+=a.x*w.z; acc[0][3]+=a.x*w.w;
      acc[1][0]+=a.y*w.x; acc[1][1]+=a.y*w.y; acc[1][2]+=a.y*w.z; acc[1][3]+=a.y*w.w;
      acc[2][0]+=a.z*w.x; acc[2][1]+=a.z*w.y; acc[2][2]+=a.z*w.z; acc[2][3]+=a.z*w.w;
      acc[3][0]+=a.w*w.x; acc[3][1]+=a.w*w.y; acc[3][2]+=a.w*w.z; acc[3][3]+=a.w*w.w;
    }
    __syncthreads();
  }
  #pragma unroll
  for (int i=0;i<4;i++){
    int m = m0 + ty*4 + i;
    #pragma unroll
    for (int j=0;j<4;j++){
      int gn = gn0 + tx*4 + j;
      g_att1[(size_t)m*ATT + gn] = acc[i][j] + bias[gn];
    }
  }
}

// per-step: [att2 | gatepre | hWhh] = h @ [W_dec_att ; W_beta ; W_hh]^T.  N=4608, K=512.
__global__ void k_hproj(const float* __restrict__ Wda, const float* __restrict__ Wbeta,
                        const float* __restrict__ Whh, int t){
  __shared__ float sA[32][68];
  __shared__ float sW[32][34];
  int tid=threadIdx.x, tx=tid&15, ty=tid>>4;
  int gn0 = blockIdx.x*32;
  int nact = g_bact[t];
  const float* Wp; float* Cp; int cs, coff;
  if (gn0 < ATT)           { Wp = Wda   + (size_t)gn0*DEC;            Cp = g_att2;    cs = ATT; coff = gn0; }
  else if (gn0 < ATT+ENC)  { Wp = Wbeta + (size_t)(gn0-ATT)*DEC;      Cp = g_gatepre; cs = ENC; coff = gn0-ATT; }
  else                     { Wp = Whh   + (size_t)(gn0-ATT-ENC)*DEC;  Cp = g_gates;   cs = G4;  coff = gn0-ATT-ENC; }
  bool act = (ty*4 < nact);
  float acc[4][2] = {};
  for (int k0=0;k0<DEC;k0+=32){
    #pragma unroll
    for (int i=0;i<2;i++){
      int lin = tid+i*256, row=lin>>3, kq=lin&7;
      float4 v = *(const float4*)(g_h + row*DEC + k0 + kq*4);
      sA[kq*4+0][row]=v.x; sA[kq*4+1][row]=v.y; sA[kq*4+2][row]=v.z; sA[kq*4+3][row]=v.w;
    }
    {
      int n=tid>>3, kq=tid&7;
      float4 v = *(const float4*)(Wp + (size_t)n*DEC + k0 + kq*4);
      sW[kq*4+0][n]=v.x; sW[kq*4+1][n]=v.y; sW[kq*4+2][n]=v.z; sW[kq*4+3][n]=v.w;
    }
    __syncthreads();
    if (act){
      #pragma unroll
      for (int k=0;k<32;k++){
        float4 a = *(const float4*)&sA[k][ty*4];
        float2 w = *(const float2*)&sW[k][tx*2];
        acc[0][0] += a.x*w.x; acc[0][1] += a.x*w.y;
        acc[1][0] += a.y*w.x; acc[1][1] += a.y*w.y;
        acc[2][0] += a.z*w.x; acc[2][1] += a.z*w.y;
        acc[3][0] += a.w*w.x; acc[3][1] += a.w*w.y;
      }
    }
    __syncthreads();
  }
  if (act){
    #pragma unroll
    for (int i=0;i<4;i++){
      int m = ty*4+i;
      if (m < nact){
        #pragma unroll
        for (int j=0;j<2;j++)
          Cp[m*cs + coff + tx*2 + j] = acc[i][j];
      }
    }
  }
}

// per-step fused attention: e -> softmax -> alpha -> awe -> gate*awe -> x (+emb gather)
__global__ void k_att(const float* __restrict__ b_dec_att, const float* __restrict__ w_full,
                      const float* __restrict__ b_full, const float* __restrict__ enc,
                      const float* __restrict__ b_beta, const float* __restrict__ emb_table,
                      const int* __restrict__ caps, float* __restrict__ alphas, int t){
  int b = blockIdx.x, tid = threadIdx.x;
  int nact = g_bact[t];
  if (b >= nact){
    for (int p=tid;p<PP;p+=256) alphas[(size_t)b*TSTEPS*PP + (size_t)t*PP + p] = 0.f;
    return;
  }
  __shared__ float s_a2[ATT];
  __shared__ float s_wf[ATT];
  __shared__ float s_e[PP];
  __shared__ float s_red[8];
  for (int a=tid;a<ATT;a+=256){
    s_a2[a] = g_att2[b*ATT + a] + b_dec_att[a];
    s_wf[a] = w_full[a];
  }
  __syncthreads();
  int warp = tid>>5, lane = tid&31;
  const float* a1 = g_att1 + (size_t)b*PP*ATT;
  float bf = b_full[0];
  for (int p=warp; p<PP; p+=8){
    const float* r = a1 + (size_t)p*ATT;
    float s=0.f;
    #pragma unroll 4
    for (int a=lane; a<ATT; a+=32)
      s += fmaxf(r[a]+s_a2[a],0.f)*s_wf[a];
    #pragma unroll
    for (int o=16;o;o>>=1) s += __shfl_xor_sync(0xffffffffu,s,o);
    if (lane==0) s_e[p] = s + bf;
  }
  __syncthreads();
  float m = -1e30f;
  for (int p=tid;p<PP;p+=256) m = fmaxf(m, s_e[p]);
  #pragma unroll
  for (int o=16;o;o>>=1) m = fmaxf(m,__shfl_xor_sync(0xffffffffu,m,o));
  if (lane==0) s_red[warp]=m;
  __syncthreads();
  float mx = s_red[0];
  #pragma unroll
  for (int i=1;i<8;i++) mx = fmaxf(mx, s_red[i]);
  __syncthreads();
  float sum=0.f;
  for (int p=tid;p<PP;p+=256){ float ex=expf(s_e[p]-mx); s_e[p]=ex; sum+=ex; }
  #pragma unroll
  for (int o=16;o;o>>=1) sum += __shfl_xor_sync(0xffffffffu,sum,o);
  if (lane==0) s_red[warp]=sum;
  __syncthreads();
  float tot = 0.f;
  #pragma unroll
  for (int i=0;i<8;i++) tot += s_red[i];
  float inv = 1.0f/tot;
  for (int p=tid;p<PP;p+=256){
    float al = s_e[p]*inv;
    s_e[p]=al;
    alphas[(size_t)b*TSTEPS*PP + (size_t)t*PP + p] = al;
  }
  __syncthreads();
  const float* eb = enc + (size_t)b*PP*ENC;
  for (int e=tid;e<ENC;e+=256){
    float c0=0.f,c1=0.f,c2=0.f,c3=0.f;
    #pragma unroll 1
    for (int p=0; p<PP; p+=4){            // 196 = 4*49 exactly
      c0 += s_e[p]  *eb[(size_t)p*ENC+e];
      c1 += s_e[p+1]*eb[(size_t)(p+1)*ENC+e];
      c2 += s_e[p+2]*eb[(size_t)(p+2)*ENC+e];
      c3 += s_e[p+3]*eb[(size_t)(p+3)*ENC+e];
    }
    float awe = (c0+c1)+(c2+c3);
    float gp = g_gatepre[b*ENC+e] + b_beta[e];
    g_x[b*XDIM + EMB + e] = sigmoidf_(gp)*awe;
  }
  int tok = caps[b*LCAP + t];
  for (int jj=tid;jj<EMB;jj+=256)
    g_x[b*XDIM + jj] = emb_table[(size_t)tok*EMB + jj];
}

// per-step: split-K partials of x @ W_ih^T.  N=2048 K=2560 (4 slices of 640).
__global__ void k_gates(const float* __restrict__ Wih, int t){
  __shared__ float sA[32][68];
  __shared__ float sW[32][34];
  int tid=threadIdx.x, tx=tid&15, ty=tid>>4;
  int gn0 = blockIdx.x*32;
  int kbase = blockIdx.z*640;
  int nact = g_bact[t];
  bool act = (ty*4 < nact);
  float acc[4][2] = {};
  for (int k0=0;k0<640;k0+=32){
    #pragma unroll
    for (int i=0;i<2;i++){
      int lin = tid+i*256, row=lin>>3, kq=lin&7;
      float4 v = *(const float4*)(g_x + (size_t)row*XDIM + kbase + k0 + kq*4);
      sA[kq*4+0][row]=v.x; sA[kq*4+1][row]=v.y; sA[kq*4+2][row]=v.z; sA[kq*4+3][row]=v.w;
    }
    {
      int n=tid>>3, kq=tid&7;
      float4 v = *(const float4*)(Wih + (size_t)(gn0+n)*XDIM + kbase + k0 + kq*4);
      sW[kq*4+0][n]=v.x; sW[kq*4+1][n]=v.y; sW[kq*4+2][n]=v.z; sW[kq*4+3][n]=v.w;
    }
    __syncthreads();
    if (act){
      #pragma unroll
      for (int k=0;k<32;k++){
        float4 a = *(const float4*)&sA[k][ty*4];
        float2 w = *(const float2*)&sW[k][tx*2];
        acc[0][0] += a.x*w.x; acc[0][1] += a.x*w.y;
        acc[1][0] += a.y*w.x; acc[1][1] += a.y*w.y;
        acc[2][0] += a.z*w.x; acc[2][1] += a.z*w.y;
        acc[3][0] += a.w*w.x; acc[3][1] += a.w*w.y;
      }
    }
    __syncthreads();
  }
  if (act){
    float* outp = g_gpart + (size_t)blockIdx.z*B*G4;
    #pragma unroll
    for (int i=0;i<4;i++){
      int mm = ty*4+i;
      if (mm < nact){
        #pragma unroll
        for (int j=0;j<2;j++)
          outp[mm*G4 + gn0 + tx*2 + j] = acc[i][j];
      }
    }
  }
}

// per-step LSTM pointwise + shrinking-batch h/c update
__global__ void k_lstm(const float* __restrict__ b_ih, const float* __restrict__ b_hh, int t){
  int b = blockIdx.x;
  if (b >= g_bact[t]) return;
  int j = threadIdx.x;
  const size_t S = (size_t)B*G4;
  int base = b*G4;
  float gi = g_gates[base+j]        + g_gpart[base+j]        + g_gpart[S+base+j]        + g_gpart[2*S+base+j]        + g_gpart[3*S+base+j]        + b_ih[j]        + b_hh[j];
  float gf = g_gates[base+DEC+j]    + g_gpart[base+DEC+j]    + g_gpart[S+base+DEC+j]    + g_gpart[2*S+base+DEC+j]    + g_gpart[3*S+base+DEC+j]    + b_ih[DEC+j]    + b_hh[DEC+j];
  float gg = g_gates[base+2*DEC+j]  + g_gpart[base+2*DEC+j]  + g_gpart[S+base+2*DEC+j]  + g_gpart[2*S+base+2*DEC+j]  + g_gpart[3*S+base+2*DEC+j]  + b_ih[2*DEC+j]  + b_hh[2*DEC+j];
  float go = g_gates[base+3*DEC+j]  + g_gpart[base+3*DEC+j]  + g_gpart[S+base+3*DEC+j]  + g_gpart[2*S+base+3*DEC+j]  + g_gpart[3*S+base+3*DEC+j]  + b_ih[3*DEC+j]  + b_hh[3*DEC+j];
  float cn = sigmoidf_(gf)*g_c[b*DEC+j] + sigmoidf_(gi)*tanhf(gg);
  float hn = sigmoidf_(go)*tanhf(cn);
  g_c[b*DEC+j]=cn; g_h[b*DEC+j]=hn;
}

// per-step vocab projection: preds[:, t, :] = h_new @ fc_W^T + fc_b (zeros for inactive rows)
__global__ void k_fc(const float* __restrict__ W, const float* __restrict__ bias,
                     float* __restrict__ preds, int t){
  __shared__ float sA[16][68];
  __shared__ float sW[16][68];
  int tid=threadIdx.x, tx=tid&15, ty=tid>>4;
  int gn0 = blockIdx.x*64;
  int nact = g_bact[t];
  bool act = (ty*4 < nact);
  float acc[4][4]={};
  for (int k0=0;k0<DEC;k0+=16){
    {
      int row=tid>>2, kq=tid&3;
      float4 v = *(const float4*)(g_h + row*DEC + k0 + kq*4);
      sA[kq*4+0][row]=v.x; sA[kq*4+1][row]=v.y; sA[kq*4+2][row]=v.z; sA[kq*4+3][row]=v.w;
    }
    {
      int n=tid>>2, kq=tid&3; int gn=gn0+n;
      float4 v = make_float4(0.f,0.f,0.f,0.f);
      if (gn < V) v = *(const float4*)(W + (size_t)gn*DEC + k0 + kq*4);
      sW[kq*4+0][n]=v.x; sW[kq*4+1][n]=v.y; sW[kq*4+2][n]=v.z; sW[kq*4+3][n]=v.w;
    }
    __syncthreads();
    if (act){
      #pragma unroll
      for (int k=0;k<16;k++){
        float4 a=*(const float4*)&sA[k][ty*4];
        float4 w=*(const float4*)&sW[k][tx*4];
        acc[0][0]+=a.x*w.x; acc[0][1]+=a.x*w.y; acc[0][2]+=a.x*w.z; acc[0][3]+=a.x*w.w;
        acc[1][0]+=a.y*w.x; acc[1][1]+=a.y*w.y; acc[1][2]+=a.y*w.z; acc[1][3]+=a.y*w.w;
        acc[2][0]+=a.z*w.x; acc[2][1]+=a.z*w.y; acc[2][2]+=a.z*w.z; acc[2][3]+=a.z*w.w;
        acc[3][0]+=a.w*w.x; acc[3][1]+=a.w*w.y; acc[3][2]+=a.w*w.z; acc[3][3]+=a.w*w.w;
      }
    }
    __syncthreads();
  }
  #pragma unroll
  for (int i=0;i<4;i++){
    int mm=ty*4+i;
    #pragma unroll
    for (int j=0;j<4;j++){
      int gn = gn0+tx*4+j;
      if (gn < V){
        float val = (mm < nact) ? (acc[i][j] + bias[gn]) : 0.0f;
        preds[(size_t)mm*TSTEPS*V + (size_t)t*V + gn] = val;
      }
    }
  }
}

// ---------------- launch ----------------
extern "C" void kernel_launch(void* const* d_in, const int* in_sizes, int n_in,
                              void* d_out, int out_size){
  (void)in_sizes; (void)n_in; (void)out_size;
  const float* enc       = (const float*)d_in[0];
  const int*   caps      = (const int*)  d_in[1];
  const int*   caplen    = (const int*)  d_in[2];
  const float* emb_table = (const float*)d_in[3];
  const float* W_enc_att = (const float*)d_in[4];
  const float* b_enc_att = (const float*)d_in[5];
  const float* W_dec_att = (const float*)d_in[6];
  const float* b_dec_att = (const float*)d_in[7];
  const float* w_full    = (const float*)d_in[8];
  const float* b_full    = (const float*)d_in[9];
  const float* W_init_h  = (const float*)d_in[10];
  const float* b_init_h  = (const float*)d_in[11];
  const float* W_init_c  = (const float*)d_in[12];
  const float* b_init_c  = (const float*)d_in[13];
  const float* W_beta    = (const float*)d_in[14];
  const float* b_beta    = (const float*)d_in[15];
  const float* W_ih      = (const float*)d_in[16];
  const float* b_ih      = (const float*)d_in[17];
  const float* W_hh      = (const float*)d_in[18];
  const float* b_hh      = (const float*)d_in[19];
  const float* fc_W      = (const float*)d_in[20];
  const float* fc_b      = (const float*)d_in[21];

  float* preds  = (float*)d_out;                       // [B, T, V]
  float* alphas = preds + (size_t)B*TSTEPS*V;          // [B, T, P]

  k_bact<<<1, 32>>>(caplen);
  k_mean<<<dim3(B, ENC/256), 256>>>(enc);
  k_init_hc<<<(2*DEC)/32, 256>>>(W_init_h, b_init_h, W_init_c, b_init_c);
  k_att1<<<dim3(ATT/64, (B*PP)/64), 256>>>(enc, W_enc_att, b_enc_att);

  for (int t=0; t<TSTEPS; t++){
    k_hproj<<<(ATT+ENC+G4)/32, 256>>>(W_dec_att, W_beta, W_hh, t);
    k_att  <<<B, 256>>>(b_dec_att, w_full, b_full, enc, b_beta, emb_table, caps, alphas, t);
    k_gates<<<dim3(G4/32, 1, 4), 256>>>(W_ih, t);
    k_lstm <<<B, DEC>>>(b_ih, b_hh, t);
    k_fc   <<<(V+63)/64, 256>>>(fc_W, fc_b, preds, t);
  }
}

// round 3
// speedup vs baseline: 2.0023x; 2.0023x over previous
#include <cuda_runtime.h>
#include <cuda_fp16.h>
#include <cstdint>

#define B      64
#define PP     196
#define ENC    2048
#define LCAP   32
#define V      20000
#define ATT    512
#define EMB    512
#define DEC    512
#define TSTEPS 31
#define XDIM   (EMB+ENC)   /* 2560 */
#define G4     (4*DEC)     /* 2048 */
#define NSLICE 8           /* split-K slices for gates */
#define KSLICE (XDIM/NSLICE) /* 320 */
#define FCBLK  157         /* ceil(20000/128) */
#define HPBLK  ((ATT+ENC+G4)/128) /* 36 */

// ---------------- device scratch ----------------
__device__ float  g_att1[(size_t)B*PP*ATT];
__device__ __half g_ench[(size_t)B*PP*ENC];
__device__ float  g_mean[B*ENC];
__device__ float  g_h[B*DEC];
__device__ float  g_c[B*DEC];
__device__ float  g_att2[B*ATT];
__device__ float  g_gatepre[B*ENC];
__device__ float  g_gates[B*G4];
__device__ float  g_gpart[(size_t)NSLICE*B*G4];
__device__ float  g_x[B*XDIM];
__device__ int    g_bact[TSTEPS];

__device__ __forceinline__ float sigmoidf_(float x){ return 1.0f/(1.0f+expf(-x)); }

// ---------------- one-time kernels ----------------
__global__ void k_bact(const int* __restrict__ caplen){
  int t = threadIdx.x;
  if (t < TSTEPS){
    int c = 0;
    for (int b=0;b<B;b++) c += ((caplen[b]-1) > t) ? 1 : 0;
    g_bact[t] = c;
  }
}

__global__ void k_cvt(const float* __restrict__ enc){
  size_t i = (size_t)blockIdx.x*blockDim.x + threadIdx.x;
  const size_t n4 = (size_t)B*PP*ENC/4;
  if (i >= n4) return;
  float4 v = ((const float4*)enc)[i];
  __half2* o = (__half2*)g_ench;
  o[i*2]   = __floats2half2_rn(v.x, v.y);
  o[i*2+1] = __floats2half2_rn(v.z, v.w);
}

__global__ void k_mean(const float* __restrict__ enc){
  int b = blockIdx.x;
  int e = blockIdx.y*256 + threadIdx.x;
  const float* p0 = enc + (size_t)b*PP*ENC + e;
  float s = 0.f;
  #pragma unroll 4
  for (int p=0;p<PP;p++) s += p0[(size_t)p*ENC];
  g_mean[b*ENC + e] = s * (1.0f/PP);
}

__global__ void k_init_hc(const float* __restrict__ Wh, const float* __restrict__ bh,
                          const float* __restrict__ Wc, const float* __restrict__ bc){
  __shared__ float sA[32][68];
  __shared__ float sW[32][34];
  int tid = threadIdx.x, tx = tid & 15, ty = tid >> 4;
  int gn0 = blockIdx.x * 32;
  const float* Wp = (gn0 < DEC) ? (Wh + (size_t)gn0*ENC) : (Wc + (size_t)(gn0-DEC)*ENC);
  float acc[4][2] = {};
  for (int k0=0; k0<ENC; k0+=32){
    #pragma unroll
    for (int i=0;i<2;i++){
      int lin = tid + i*256, row = lin >> 3, kq = lin & 7;
      float4 v = *(const float4*)(g_mean + row*ENC + k0 + kq*4);
      sA[kq*4+0][row]=v.x; sA[kq*4+1][row]=v.y; sA[kq*4+2][row]=v.z; sA[kq*4+3][row]=v.w;
    }
    {
      int n = tid >> 3, kq = tid & 7;
      float4 v = *(const float4*)(Wp + (size_t)n*ENC + k0 + kq*4);
      sW[kq*4+0][n]=v.x; sW[kq*4+1][n]=v.y; sW[kq*4+2][n]=v.z; sW[kq*4+3][n]=v.w;
    }
    __syncthreads();
    #pragma unroll
    for (int k=0;k<32;k++){
      float4 a = *(const float4*)&sA[k][ty*4];
      float2 w = *(const float2*)&sW[k][tx*2];
      acc[0][0]+=a.x*w.x; acc[0][1]+=a.x*w.y;
      acc[1][0]+=a.y*w.x; acc[1][1]+=a.y*w.y;
      acc[2][0]+=a.z*w.x; acc[2][1]+=a.z*w.y;
      acc[3][0]+=a.w*w.x; acc[3][1]+=a.w*w.y;
    }
    __syncthreads();
  }
  #pragma unroll
  for (int i=0;i<4;i++){
    int m = ty*4+i;
    #pragma unroll
    for (int j=0;j<2;j++){
      int gn = gn0 + tx*2 + j;
      if (gn < DEC) g_h[m*DEC + gn]       = acc[i][j] + bh[gn];
      else          g_c[m*DEC + (gn-DEC)] = acc[i][j] + bc[gn-DEC];
    }
  }
}

// att1: BM=128 BN=128 BK=16, 8x8 microtile, register-prefetch pipelined
__global__ void __launch_bounds__(256) k_att1(const float* __restrict__ A, const float* __restrict__ W,
                       const float* __restrict__ bias){
  __shared__ float sA[16*132];
  __shared__ float sW[16*132];
  int tid=threadIdx.x, tx=tid&15, ty=tid>>4;
  int m0=blockIdx.y*128, gn0=blockIdx.x*128;
  int r0=tid>>2, kq=tid&3;
  int r1=r0+64;
  const float* Ap0 = A + (size_t)(m0+r0)*ENC + kq*4;
  const float* Ap1 = A + (size_t)(m0+r1)*ENC + kq*4;
  const float* Wp0 = W + (size_t)(gn0+r0)*ENC + kq*4;
  const float* Wp1 = W + (size_t)(gn0+r1)*ENC + kq*4;
  float4 a0=*(const float4*)Ap0, a1=*(const float4*)Ap1;
  float4 w0=*(const float4*)Wp0, w1=*(const float4*)Wp1;
  float acc[8][8]={};
  for (int k0=0;k0<ENC;k0+=16){
    sA[(kq*4+0)*132+r0]=a0.x; sA[(kq*4+1)*132+r0]=a0.y; sA[(kq*4+2)*132+r0]=a0.z; sA[(kq*4+3)*132+r0]=a0.w;
    sA[(kq*4+0)*132+r1]=a1.x; sA[(kq*4+1)*132+r1]=a1.y; sA[(kq*4+2)*132+r1]=a1.z; sA[(kq*4+3)*132+r1]=a1.w;
    sW[(kq*4+0)*132+r0]=w0.x; sW[(kq*4+1)*132+r0]=w0.y; sW[(kq*4+2)*132+r0]=w0.z; sW[(kq*4+3)*132+r0]=w0.w;
    sW[(kq*4+0)*132+r1]=w1.x; sW[(kq*4+1)*132+r1]=w1.y; sW[(kq*4+2)*132+r1]=w1.z; sW[(kq*4+3)*132+r1]=w1.w;
    __syncthreads();
    if (k0+16<ENC){
      a0=*(const float4*)(Ap0+k0+16); a1=*(const float4*)(Ap1+k0+16);
      w0=*(const float4*)(Wp0+k0+16); w1=*(const float4*)(Wp1+k0+16);
    }
    #pragma unroll
    for (int k=0;k<16;k++){
      float4 xa=*(const float4*)&sA[k*132+ty*8];
      float4 xb=*(const float4*)&sA[k*132+ty*8+4];
      float4 ya=*(const float4*)&sW[k*132+tx*8];
      float4 yb=*(const float4*)&sW[k*132+tx*8+4];
      float av[8]={xa.x,xa.y,xa.z,xa.w,xb.x,xb.y,xb.z,xb.w};
      float wv[8]={ya.x,ya.y,ya.z,ya.w,yb.x,yb.y,yb.z,yb.w};
      #pragma unroll
      for (int i=0;i<8;i++)
        #pragma unroll
        for (int j=0;j<8;j++)
          acc[i][j] += av[i]*wv[j];
    }
    __syncthreads();
  }
  #pragma unroll
  for (int i=0;i<8;i++){
    int m = m0 + ty*8 + i;
    int gn = gn0 + tx*8;
    float4 o0 = make_float4(acc[i][0]+bias[gn],   acc[i][1]+bias[gn+1],
                            acc[i][2]+bias[gn+2], acc[i][3]+bias[gn+3]);
    float4 o1 = make_float4(acc[i][4]+bias[gn+4], acc[i][5]+bias[gn+5],
                            acc[i][6]+bias[gn+6], acc[i][7]+bias[gn+7]);
    *(float4*)(g_att1 + (size_t)m*ATT + gn)     = o0;
    *(float4*)(g_att1 + (size_t)m*ATT + gn + 4) = o1;
  }
}

// ---- device GEMM bodies for the merged per-step kernel ----
// hproj: [att2|gatepre|hWhh] tile, BM=64 BN=128 BK=32
__device__ __forceinline__ void hproj_dev(float* sbuf, int gn0, int t,
    const float* __restrict__ Wda, const float* __restrict__ Wbeta, const float* __restrict__ Whh){
  float* sA = sbuf;            // [32][68]
  float* sW = sbuf + 32*68;    // [32][132]
  int tid=threadIdx.x, tx=tid&15, ty=tid>>4;
  int nact = g_bact[t];
  bool act = (ty*4 < nact);
  const float* Wp; float* Cp; int cs, coff;
  if (gn0 < ATT)          { Wp = Wda   + (size_t)gn0*DEC;           Cp = g_att2;    cs = ATT; coff = gn0; }
  else if (gn0 < ATT+ENC) { Wp = Wbeta + (size_t)(gn0-ATT)*DEC;     Cp = g_gatepre; cs = ENC; coff = gn0-ATT; }
  else                    { Wp = Whh   + (size_t)(gn0-ATT-ENC)*DEC; Cp = g_gates;   cs = G4;  coff = gn0-ATT-ENC; }
  int rA0 = tid>>3,        kqA0 = tid&7;
  int rA1 = (tid+256)>>3,  kqA1 = (tid+256)&7;
  const float* ApA0 = g_h + rA0*DEC + kqA0*4;
  const float* ApA1 = g_h + rA1*DEC + kqA1*4;
  int rW = tid>>3, kqW = tid&7;
  float4 pa0=*(const float4*)ApA0, pa1=*(const float4*)ApA1;
  float4 pw[4];
  #pragma unroll
  for (int i=0;i<4;i++) pw[i] = *(const float4*)(Wp + (size_t)(rW + i*32)*DEC + kqW*4);
  float acc[4][8]={};
  for (int k0=0;k0<DEC;k0+=32){
    sA[(kqA0*4+0)*68+rA0]=pa0.x; sA[(kqA0*4+1)*68+rA0]=pa0.y; sA[(kqA0*4+2)*68+rA0]=pa0.z; sA[(kqA0*4+3)*68+rA0]=pa0.w;
    sA[(kqA1*4+0)*68+rA1]=pa1.x; sA[(kqA1*4+1)*68+rA1]=pa1.y; sA[(kqA1*4+2)*68+rA1]=pa1.z; sA[(kqA1*4+3)*68+rA1]=pa1.w;
    #pragma unroll
    for (int i=0;i<4;i++){
      int n = rW + i*32;
      sW[(kqW*4+0)*132+n]=pw[i].x; sW[(kqW*4+1)*132+n]=pw[i].y; sW[(kqW*4+2)*132+n]=pw[i].z; sW[(kqW*4+3)*132+n]=pw[i].w;
    }
    __syncthreads();
    if (k0+32<DEC){
      pa0=*(const float4*)(ApA0+k0+32); pa1=*(const float4*)(ApA1+k0+32);
      #pragma unroll
      for (int i=0;i<4;i++) pw[i] = *(const float4*)(Wp + (size_t)(rW + i*32)*DEC + kqW*4 + k0+32);
    }
    if (act){
      #pragma unroll
      for (int k=0;k<32;k++){
        float4 a=*(const float4*)&sA[k*68+ty*4];
        float4 ya=*(const float4*)&sW[k*132+tx*8];
        float4 yb=*(const float4*)&sW[k*132+tx*8+4];
        float av[4]={a.x,a.y,a.z,a.w};
        float wv[8]={ya.x,ya.y,ya.z,ya.w,yb.x,yb.y,yb.z,yb.w};
        #pragma unroll
        for (int i=0;i<4;i++)
          #pragma unroll
          for (int j=0;j<8;j++)
            acc[i][j] += av[i]*wv[j];
      }
    }
    __syncthreads();
  }
  if (act){
    #pragma unroll
    for (int i=0;i<4;i++){
      int m = ty*4+i;
      if (m < nact){
        float4 o0 = make_float4(acc[i][0],acc[i][1],acc[i][2],acc[i][3]);
        float4 o1 = make_float4(acc[i][4],acc[i][5],acc[i][6],acc[i][7]);
        *(float4*)(Cp + (size_t)m*cs + coff + tx*8)     = o0;
        *(float4*)(Cp + (size_t)m*cs + coff + tx*8 + 4) = o1;
      }
    }
  }
}

// fc tile: BM=64 BN=128 BK=16
__device__ __forceinline__ void fc_dev(float* sbuf, int gn0, int t,
    const float* __restrict__ W, const float* __restrict__ bias, float* __restrict__ preds){
  float* sA = sbuf;           // [16][68]
  float* sW = sbuf + 16*68;   // [16][132]
  int tid=threadIdx.x, tx=tid&15, ty=tid>>4;
  int nact = g_bact[t];
  bool act = (ty*4 < nact);
  int rA = tid>>2, kq = tid&3;
  const float* Ap = g_h + rA*DEC + kq*4;
  int wn0 = gn0 + rA;      if (wn0 >= V) wn0 = V-1;
  int wn1 = gn0 + rA + 64; if (wn1 >= V) wn1 = V-1;
  const float* Wq0 = W + (size_t)wn0*DEC + kq*4;
  const float* Wq1 = W + (size_t)wn1*DEC + kq*4;
  float4 a=*(const float4*)Ap, w0=*(const float4*)Wq0, w1=*(const float4*)Wq1;
  float acc[4][8]={};
  for (int k0=0;k0<DEC;k0+=16){
    sA[(kq*4+0)*68+rA]=a.x; sA[(kq*4+1)*68+rA]=a.y; sA[(kq*4+2)*68+rA]=a.z; sA[(kq*4+3)*68+rA]=a.w;
    sW[(kq*4+0)*132+rA]=w0.x;    sW[(kq*4+1)*132+rA]=w0.y;    sW[(kq*4+2)*132+rA]=w0.z;    sW[(kq*4+3)*132+rA]=w0.w;
    sW[(kq*4+0)*132+rA+64]=w1.x; sW[(kq*4+1)*132+rA+64]=w1.y; sW[(kq*4+2)*132+rA+64]=w1.z; sW[(kq*4+3)*132+rA+64]=w1.w;
    __syncthreads();
    if (k0+16<DEC){
      a=*(const float4*)(Ap+k0+16); w0=*(const float4*)(Wq0+k0+16); w1=*(const float4*)(Wq1+k0+16);
    }
    if (act){
      #pragma unroll
      for (int k=0;k<16;k++){
        float4 av4=*(const float4*)&sA[k*68+ty*4];
        float4 ya=*(const float4*)&sW[k*132+tx*8];
        float4 yb=*(const float4*)&sW[k*132+tx*8+4];
        float av[4]={av4.x,av4.y,av4.z,av4.w};
        float wv[8]={ya.x,ya.y,ya.z,ya.w,yb.x,yb.y,yb.z,yb.w};
        #pragma unroll
        for (int i=0;i<4;i++)
          #pragma unroll
          for (int j=0;j<8;j++)
            acc[i][j] += av[i]*wv[j];
      }
    }
    __syncthreads();
  }
  #pragma unroll
  for (int i=0;i<4;i++){
    int mm = ty*4+i;
    float* orow = preds + (size_t)mm*TSTEPS*V + (size_t)t*V;
    #pragma unroll
    for (int j=0;j<8;j++){
      int gn = gn0 + tx*8 + j;
      if (gn < V)
        orow[gn] = (mm < nact) ? (acc[i][j] + bias[gn]) : 0.0f;
    }
  }
}

// merged launch: blocks [0,FCBLK) do fc(t-1); blocks [FCBLK, FCBLK+HPBLK) do hproj(t)
__global__ void __launch_bounds__(256) k_fc_hproj(
    const float* __restrict__ fcW, const float* __restrict__ fcb, float* __restrict__ preds,
    const float* __restrict__ Wda, const float* __restrict__ Wbeta, const float* __restrict__ Whh,
    int t){
  __shared__ __align__(16) float sbuf[32*68 + 32*132];
  if ((int)blockIdx.x < FCBLK) fc_dev(sbuf, blockIdx.x*128, t-1, fcW, fcb, preds);
  else                         hproj_dev(sbuf, (blockIdx.x-FCBLK)*128, t, Wda, Wbeta, Whh);
}
__global__ void __launch_bounds__(256) k_hproj_only(
    const float* __restrict__ Wda, const float* __restrict__ Wbeta, const float* __restrict__ Whh, int t){
  __shared__ __align__(16) float sbuf[32*68 + 32*132];
  hproj_dev(sbuf, blockIdx.x*128, t, Wda, Wbeta, Whh);
}
__global__ void __launch_bounds__(256) k_fc_only(
    const float* __restrict__ fcW, const float* __restrict__ fcb, float* __restrict__ preds, int t){
  __shared__ __align__(16) float sbuf[16*68 + 16*132];
  fc_dev(sbuf, blockIdx.x*128, t, fcW, fcb, preds);
}

// per-step: e -> softmax -> alphas, + embedding gather
__global__ void k_alpha(const float* __restrict__ b_dec_att, const float* __restrict__ w_full,
                        const float* __restrict__ b_full, const float* __restrict__ emb_table,
                        const int* __restrict__ caps, float* __restrict__ alphas, int t){
  int b = blockIdx.x, tid = threadIdx.x;
  int nact = g_bact[t];
  if (b >= nact){
    for (int p=tid;p<PP;p+=256) alphas[(size_t)b*TSTEPS*PP + (size_t)t*PP + p] = 0.f;
    return;
  }
  __shared__ float s_a2[ATT];
  __shared__ float s_wf[ATT];
  __shared__ float s_e[PP];
  __shared__ float s_red[8];
  for (int a=tid;a<ATT;a+=256){
    s_a2[a] = g_att2[b*ATT + a] + b_dec_att[a];
    s_wf[a] = w_full[a];
  }
  __syncthreads();
  int warp = tid>>5, lane = tid&31;
  const float* a1 = g_att1 + (size_t)b*PP*ATT;
  float bf = b_full[0];
  for (int p=warp; p<PP; p+=8){
    const float* r = a1 + (size_t)p*ATT;
    float s=0.f;
    #pragma unroll 4
    for (int a=lane; a<ATT; a+=32)
      s += fmaxf(r[a]+s_a2[a],0.f)*s_wf[a];
    #pragma unroll
    for (int o=16;o;o>>=1) s += __shfl_xor_sync(0xffffffffu,s,o);
    if (lane==0) s_e[p] = s + bf;
  }
  __syncthreads();
  float m = -1e30f;
  for (int p=tid;p<PP;p+=256) m = fmaxf(m, s_e[p]);
  #pragma unroll
  for (int o=16;o;o>>=1) m = fmaxf(m,__shfl_xor_sync(0xffffffffu,m,o));
  if (lane==0) s_red[warp]=m;
  __syncthreads();
  float mx = s_red[0];
  #pragma unroll
  for (int i=1;i<8;i++) mx = fmaxf(mx, s_red[i]);
  __syncthreads();
  float sum=0.f;
  for (int p=tid;p<PP;p+=256){ float ex=expf(s_e[p]-mx); s_e[p]=ex; sum+=ex; }
  #pragma unroll
  for (int o=16;o;o>>=1) sum += __shfl_xor_sync(0xffffffffu,sum,o);
  if (lane==0) s_red[warp]=sum;
  __syncthreads();
  float tot = 0.f;
  #pragma unroll
  for (int i=0;i<8;i++) tot += s_red[i];
  float inv = 1.0f/tot;
  for (int p=tid;p<PP;p+=256)
    alphas[(size_t)b*TSTEPS*PP + (size_t)t*PP + p] = s_e[p]*inv;
  int tok = caps[b*LCAP + t];
  for (int jj=tid;jj<EMB;jj+=256)
    g_x[b*XDIM + jj] = emb_table[(size_t)tok*EMB + jj];
}

// per-step: awe + gate -> g_x[:, EMB:]
__global__ void k_awe(const float* __restrict__ b_beta, const float* __restrict__ alphas, int t){
  int b = blockIdx.x;
  if (b >= g_bact[t]) return;
  int tid = threadIdx.x;
  __shared__ float s_al[PP];
  const float* ap = alphas + (size_t)b*TSTEPS*PP + (size_t)t*PP;
  for (int p=tid;p<PP;p+=256) s_al[p] = ap[p];
  __syncthreads();
  int e2 = blockIdx.y*256 + tid;
  const __half2* eb = (const __half2*)g_ench + (size_t)b*PP*(ENC/2) + e2;
  float ax=0.f, ay=0.f, bx=0.f, by=0.f;
  #pragma unroll 1
  for (int p=0;p<PP;p+=4){
    float2 f0 = __half22float2(eb[(size_t) p   *(ENC/2)]);
    float2 f1 = __half22float2(eb[(size_t)(p+1)*(ENC/2)]);
    float2 f2 = __half22float2(eb[(size_t)(p+2)*(ENC/2)]);
    float2 f3 = __half22float2(eb[(size_t)(p+3)*(ENC/2)]);
    ax += s_al[p]*f0.x   + s_al[p+1]*f1.x;
    ay += s_al[p]*f0.y   + s_al[p+1]*f1.y;
    bx += s_al[p+2]*f2.x + s_al[p+3]*f3.x;
    by += s_al[p+2]*f2.y + s_al[p+3]*f3.y;
  }
  int e = e2*2;
  float g0 = sigmoidf_(g_gatepre[b*ENC+e]   + b_beta[e]);
  float g1 = sigmoidf_(g_gatepre[b*ENC+e+1] + b_beta[e+1]);
  *(float2*)(g_x + (size_t)b*XDIM + EMB + e) = make_float2(g0*(ax+bx), g1*(ay+by));
}

// per-step: split-K partials of x @ W_ih^T.  BM=64 BN=128 BK=32, NSLICE K-slices.
__global__ void __launch_bounds__(256) k_gates(const float* __restrict__ Wih, int t){
  __shared__ __align__(16) float sbuf[32*68 + 32*132];
  float* sA = sbuf;
  float* sW = sbuf + 32*68;
  int tid=threadIdx.x, tx=tid&15, ty=tid>>4;
  int gn0 = blockIdx.x*128;
  int kbase = blockIdx.z*KSLICE;
  int nact = g_bact[t];
  bool act = (ty*4 < nact);
  int rA0 = tid>>3,        kqA0 = tid&7;
  int rA1 = (tid+256)>>3,  kqA1 = (tid+256)&7;
  const float* ApA0 = g_x + (size_t)rA0*XDIM + kbase + kqA0*4;
  const float* ApA1 = g_x + (size_t)rA1*XDIM + kbase + kqA1*4;
  int rW = tid>>3, kqW = tid&7;
  const float* Wp = Wih + (size_t)gn0*XDIM + kbase;
  float4 pa0=*(const float4*)ApA0, pa1=*(const float4*)ApA1;
  float4 pw[4];
  #pragma unroll
  for (int i=0;i<4;i++) pw[i] = *(const float4*)(Wp + (size_t)(rW + i*32)*XDIM + kqW*4);
  float acc[4][8]={};
  for (int k0=0;k0<KSLICE;k0+=32){
    sA[(kqA0*4+0)*68+rA0]=pa0.x; sA[(kqA0*4+1)*68+rA0]=pa0.y; sA[(kqA0*4+2)*68+rA0]=pa0.z; sA[(kqA0*4+3)*68+rA0]=pa0.w;
    sA[(kqA1*4+0)*68+rA1]=pa1.x; sA[(kqA1*4+1)*68+rA1]=pa1.y; sA[(kqA1*4+2)*68+rA1]=pa1.z; sA[(kqA1*4+3)*68+rA1]=pa1.w;
    #pragma unroll
    for (int i=0;i<4;i++){
      int n = rW + i*32;
      sW[(kqW*4+0)*132+n]=pw[i].x; sW[(kqW*4+1)*132+n]=pw[i].y; sW[(kqW*4+2)*132+n]=pw[i].z; sW[(kqW*4+3)*132+n]=pw[i].w;
    }
    __syncthreads();
    if (k0+32<KSLICE){
      pa0=*(const float4*)(ApA0+k0+32); pa1=*(const float4*)(ApA1+k0+32);
      #pragma unroll
      for (int i=0;i<4;i++) pw[i] = *(const float4*)(Wp + (size_t)(rW + i*32)*XDIM + kqW*4 + k0+32);
    }
    if (act){
      #pragma unroll
      for (int k=0;k<32;k++){
        float4 a=*(const float4*)&sA[k*68+ty*4];
        float4 ya=*(const float4*)&sW[k*132+tx*8];
        float4 yb=*(const float4*)&sW[k*132+tx*8+4];
        float av[4]={a.x,a.y,a.z,a.w};
        float wv[8]={ya.x,ya.y,ya.z,ya.w,yb.x,yb.y,yb.z,yb.w};
        #pragma unroll
        for (int i=0;i<4;i++)
          #pragma unroll
          for (int j=0;j<8;j++)
            acc[i][j] += av[i]*wv[j];
      }
    }
    __syncthreads();
  }
  if (act){
    float* outp = g_gpart + (size_t)blockIdx.z*B*G4;
    #pragma unroll
    for (int i=0;i<4;i++){
      int mm = ty*4+i;
      if (mm < nact){
        *(float4*)(outp + (size_t)mm*G4 + gn0 + tx*8)     = make_float4(acc[i][0],acc[i][1],acc[i][2],acc[i][3]);
        *(float4*)(outp + (size_t)mm*G4 + gn0 + tx*8 + 4) = make_float4(acc[i][4],acc[i][5],acc[i][6],acc[i][7]);
      }
    }
  }
}

// per-step LSTM pointwise
__global__ void k_lstm(const float* __restrict__ b_ih, const float* __restrict__ b_hh, int t){
  int b = blockIdx.x;
  if (b >= g_bact[t]) return;
  int j = threadIdx.x;
  const size_t S = (size_t)B*G4;
  int base = b*G4;
  float g[4];
  #pragma unroll
  for (int q=0;q<4;q++){
    int off = base + q*DEC + j;
    float v = g_gates[off] + b_ih[q*DEC+j] + b_hh[q*DEC+j];
    #pragma unroll
    for (int s=0;s<NSLICE;s++) v += g_gpart[(size_t)s*S + off];
    g[q] = v;
  }
  float cn = sigmoidf_(g[1])*g_c[b*DEC+j] + sigmoidf_(g[0])*tanhf(g[2]);
  float hn = sigmoidf_(g[3])*tanhf(cn);
  g_c[b*DEC+j]=cn; g_h[b*DEC+j]=hn;
}

// ---------------- launch ----------------
extern "C" void kernel_launch(void* const* d_in, const int* in_sizes, int n_in,
                              void* d_out, int out_size){
  (void)in_sizes; (void)n_in; (void)out_size;
  const float* enc       = (const float*)d_in[0];
  const int*   caps      = (const int*)  d_in[1];
  const int*   caplen    = (const int*)  d_in[2];
  const float* emb_table = (const float*)d_in[3];
  const float* W_enc_att = (const float*)d_in[4];
  const float* b_enc_att = (const float*)d_in[5];
  const float* W_dec_att = (const float*)d_in[6];
  const float* b_dec_att = (const float*)d_in[7];
  const float* w_full    = (const float*)d_in[8];
  const float* b_full    = (const float*)d_in[9];
  const float* W_init_h  = (const float*)d_in[10];
  const float* b_init_h  = (const float*)d_in[11];
  const float* W_init_c  = (const float*)d_in[12];
  const float* b_init_c  = (const float*)d_in[13];
  const float* W_beta    = (const float*)d_in[14];
  const float* b_beta    = (const float*)d_in[15];
  const float* W_ih      = (const float*)d_in[16];
  const float* b_ih      = (const float*)d_in[17];
  const float* W_hh      = (const float*)d_in[18];
  const float* b_hh      = (const float*)d_in[19];
  const float* fc_W      = (const float*)d_in[20];
  const float* fc_b      = (const float*)d_in[21];

  float* preds  = (float*)d_out;                       // [B, T, V]
  float* alphas = preds + (size_t)B*TSTEPS*V;          // [B, T, P]

  k_bact<<<1, 32>>>(caplen);
  k_cvt<<<(int)(((size_t)B*PP*ENC/4 + 255)/256), 256>>>(enc);
  k_mean<<<dim3(B, ENC/256), 256>>>(enc);
  k_init_hc<<<(2*DEC)/32, 256>>>(W_init_h, b_init_h, W_init_c, b_init_c);
  k_att1<<<dim3(ATT/128, (B*PP)/128), 256>>>(enc, W_enc_att, b_enc_att);

  for (int t=0; t<TSTEPS; t++){
    if (t == 0)
      k_hproj_only<<<HPBLK, 256>>>(W_dec_att, W_beta, W_hh, t);
    else
      k_fc_hproj<<<FCBLK+HPBLK, 256>>>(fc_W, fc_b, preds, W_dec_att, W_beta, W_hh, t);
    k_alpha<<<B, 256>>>(b_dec_att, w_full, b_full, emb_table, caps, alphas, t);
    k_awe  <<<dim3(B, ENC/512), 256>>>(b_beta, alphas, t);
    k_gates<<<dim3(G4/128, 1, NSLICE), 256>>>(W_ih, t);
    k_lstm <<<B, DEC>>>(b_ih, b_hh, t);
  }
  k_fc_only<<<FCBLK, 256>>>(fc_W, fc_b, preds, TSTEPS-1);
}

// round 4
// speedup vs baseline: 2.1882x; 1.0928x over previous
#include <cuda_runtime.h>
#include <cuda_fp16.h>
#include <cstdint>

#define B      64
#define PP     196
#define ENC    2048
#define LCAP   32
#define V      20000
#define ATT    512
#define EMB    512
#define DEC    512
#define TSTEPS 31
#define XDIM   (EMB+ENC)   /* 2560 */
#define G4     (4*DEC)     /* 2048 */
#define NSLICE 8
#define KSLICE (XDIM/NSLICE) /* 320 */
#define FCBLK  157         /* ceil(20000/128) */
#define HPBLK  ((ATT+ENC+G4)/128) /* 36 */

// ---------------- device scratch ----------------
__device__ float  g_att1[(size_t)B*PP*ATT];
__device__ __half g_ench[(size_t)B*PP*ENC];
__device__ float  g_mean[B*ENC];
__device__ float  g_h[B*DEC];
__device__ float  g_c[B*DEC];
__device__ float  g_att2[B*ATT];
__device__ float  g_gatepre[B*ENC];
__device__ float  g_gates[B*G4];
__device__ float  g_gpart[(size_t)NSLICE*B*G4];
__device__ float  g_x[B*XDIM];
__device__ float  g_ipart[4*64*1024];
__device__ int    g_bact[TSTEPS];

__device__ __forceinline__ float sigmoidf_(float x){ return 1.0f/(1.0f+expf(-x)); }

__device__ __forceinline__ uint32_t f2tf(float f){
  uint32_t u; asm("cvt.rna.tf32.f32 %0, %1;" : "=r"(u) : "f"(f)); return u;
}
__device__ __forceinline__ void mma_tf32(float* d, const uint32_t* a, const uint32_t* b){
  asm volatile("mma.sync.aligned.m16n8k8.row.col.f32.tf32.tf32.f32 "
    "{%0,%1,%2,%3},{%4,%5,%6,%7},{%8,%9},{%0,%1,%2,%3};"
    : "+f"(d[0]),"+f"(d[1]),"+f"(d[2]),"+f"(d[3])
    : "r"(a[0]),"r"(a[1]),"r"(a[2]),"r"(a[3]),"r"(b[0]),"r"(b[1]));
}

// ---------------- one-time kernels ----------------
__global__ void k_bact(const int* __restrict__ caplen){
  int t = threadIdx.x;
  if (t < TSTEPS){
    int c = 0;
    for (int b=0;b<B;b++) c += ((caplen[b]-1) > t) ? 1 : 0;
    g_bact[t] = c;
  }
}

__global__ void k_cvt(const float* __restrict__ enc){
  size_t i = (size_t)blockIdx.x*blockDim.x + threadIdx.x;
  const size_t n4 = (size_t)B*PP*ENC/4;
  if (i >= n4) return;
  float4 v = ((const float4*)enc)[i];
  __half2* o = (__half2*)g_ench;
  o[i*2]   = __floats2half2_rn(v.x, v.y);
  o[i*2+1] = __floats2half2_rn(v.z, v.w);
}

__global__ void k_mean(const float* __restrict__ enc){
  int b = blockIdx.x;
  int e = blockIdx.y*256 + threadIdx.x;
  const float* p0 = enc + (size_t)b*PP*ENC + e;
  float s = 0.f;
  #pragma unroll 4
  for (int p=0;p<PP;p++) s += p0[(size_t)p*ENC];
  g_mean[b*ENC + e] = s * (1.0f/PP);
}

// init h0/c0: split-K partials. grid (32, 1, 4)
__global__ void k_init(const float* __restrict__ Wh, const float* __restrict__ Wc){
  __shared__ float sA[32][68];
  __shared__ float sW[32][34];
  int tid = threadIdx.x, tx = tid & 15, ty = tid >> 4;
  int gn0 = blockIdx.x * 32;
  int ks  = blockIdx.z;
  const float* Wp = (gn0 < DEC) ? (Wh + (size_t)gn0*ENC) : (Wc + (size_t)(gn0-DEC)*ENC);
  float acc[4][2] = {};
  for (int k0=ks*512; k0<ks*512+512; k0+=32){
    #pragma unroll
    for (int i=0;i<2;i++){
      int lin = tid + i*256, row = lin >> 3, kq = lin & 7;
      float4 v = *(const float4*)(g_mean + row*ENC + k0 + kq*4);
      sA[kq*4+0][row]=v.x; sA[kq*4+1][row]=v.y; sA[kq*4+2][row]=v.z; sA[kq*4+3][row]=v.w;
    }
    {
      int n = tid >> 3, kq = tid & 7;
      float4 v = *(const float4*)(Wp + (size_t)n*ENC + k0 + kq*4);
      sW[kq*4+0][n]=v.x; sW[kq*4+1][n]=v.y; sW[kq*4+2][n]=v.z; sW[kq*4+3][n]=v.w;
    }
    __syncthreads();
    #pragma unroll
    for (int k=0;k<32;k++){
      float4 a = *(const float4*)&sA[k][ty*4];
      float2 w = *(const float2*)&sW[k][tx*2];
      acc[0][0]+=a.x*w.x; acc[0][1]+=a.x*w.y;
      acc[1][0]+=a.y*w.x; acc[1][1]+=a.y*w.y;
      acc[2][0]+=a.z*w.x; acc[2][1]+=a.z*w.y;
      acc[3][0]+=a.w*w.x; acc[3][1]+=a.w*w.y;
    }
    __syncthreads();
  }
  #pragma unroll
  for (int i=0;i<4;i++){
    int m = ty*4+i;
    #pragma unroll
    for (int j=0;j<2;j++)
      g_ipart[(size_t)ks*64*1024 + m*1024 + gn0 + tx*2 + j] = acc[i][j];
  }
}

__global__ void k_init_red(const float* __restrict__ bh, const float* __restrict__ bc){
  int m = blockIdx.x;
  for (int c=threadIdx.x; c<1024; c+=256){
    float v = g_ipart[m*1024+c] + g_ipart[64*1024 + m*1024+c]
            + g_ipart[2*64*1024 + m*1024+c] + g_ipart[3*64*1024 + m*1024+c];
    if (c < DEC) g_h[m*DEC + c]       = v + bh[c];
    else         g_c[m*DEC + (c-DEC)] = v + bc[c-DEC];
  }
}

// att1 via tf32 tensor cores: BM=64 BN=128, 8 warps (4m x 2n), each warp m16 x n64
__global__ void __launch_bounds__(256) k_att1_tc(const float* __restrict__ A,
                                                 const float* __restrict__ W,
                                                 const float* __restrict__ bias){
  __shared__ uint32_t sA[64*17];
  __shared__ uint32_t sW[128*17];
  int tid=threadIdx.x, lane=tid&31, wp=tid>>5;
  int mr=wp>>1, nc=wp&1;
  int m0=blockIdx.y*64, gn0=blockIdx.x*128;
  int lr=tid>>2, kq=(tid&3)*4;
  const float* Ap  = A + (size_t)(m0+lr)*ENC + kq;
  const float* Wp0 = W + (size_t)(gn0+lr)*ENC + kq;
  const float* Wp1 = W + (size_t)(gn0+lr+64)*ENC + kq;
  float4 a=*(const float4*)Ap, w0=*(const float4*)Wp0, w1=*(const float4*)Wp1;
  float acc[8][4];
  #pragma unroll
  for (int j=0;j<8;j++){ acc[j][0]=acc[j][1]=acc[j][2]=acc[j][3]=0.f; }
  for (int k0=0;k0<ENC;k0+=16){
    sA[lr*17+kq+0]=f2tf(a.x); sA[lr*17+kq+1]=f2tf(a.y); sA[lr*17+kq+2]=f2tf(a.z); sA[lr*17+kq+3]=f2tf(a.w);
    sW[lr*17+kq+0]=f2tf(w0.x); sW[lr*17+kq+1]=f2tf(w0.y); sW[lr*17+kq+2]=f2tf(w0.z); sW[lr*17+kq+3]=f2tf(w0.w);
    sW[(lr+64)*17+kq+0]=f2tf(w1.x); sW[(lr+64)*17+kq+1]=f2tf(w1.y); sW[(lr+64)*17+kq+2]=f2tf(w1.z); sW[(lr+64)*17+kq+3]=f2tf(w1.w);
    __syncthreads();
    if (k0+16<ENC){
      a=*(const float4*)(Ap+k0+16); w0=*(const float4*)(Wp0+k0+16); w1=*(const float4*)(Wp1+k0+16);
    }
    #pragma unroll
    for (int kk=0;kk<16;kk+=8){
      uint32_t af[4];
      int r=mr*16+(lane>>2), c=kk+(lane&3);
      af[0]=sA[r*17+c]; af[1]=sA[(r+8)*17+c]; af[2]=sA[r*17+c+4]; af[3]=sA[(r+8)*17+c+4];
      #pragma unroll
      for (int j=0;j<8;j++){
        int n=nc*64+j*8+(lane>>2);
        uint32_t bf[2]={ sW[n*17+c], sW[n*17+c+4] };
        mma_tf32(acc[j], af, bf);
      }
    }
    __syncthreads();
  }
  int r0=m0+mr*16+(lane>>2), c0=(lane&3)*2;
  #pragma unroll
  for (int j=0;j<8;j++){
    int gn=gn0+nc*64+j*8+c0;
    g_att1[(size_t)r0*ATT+gn]       = acc[j][0]+bias[gn];
    g_att1[(size_t)r0*ATT+gn+1]     = acc[j][1]+bias[gn+1];
    g_att1[(size_t)(r0+8)*ATT+gn]   = acc[j][2]+bias[gn];
    g_att1[(size_t)(r0+8)*ATT+gn+1] = acc[j][3]+bias[gn+1];
  }
}

// fc via tf32 tensor cores (device body; M=64, BN=128, K=512)
__device__ __forceinline__ void fc_tc_dev(uint32_t* sbuf, int gn0, int t,
    const float* __restrict__ W, const float* __restrict__ bias, float* __restrict__ preds){
  uint32_t* sA = sbuf;          // [64][17]
  uint32_t* sW = sbuf + 64*17;  // [128][17]
  int tid=threadIdx.x, lane=tid&31, wp=tid>>5;
  int mr=wp>>1, nc=wp&1;
  int nact = g_bact[t];
  int lr=tid>>2, kq=(tid&3)*4;
  const float* Ap = g_h + lr*DEC + kq;
  int wn0 = gn0 + lr;      if (wn0 >= V) wn0 = V-1;
  int wn1 = gn0 + lr + 64; if (wn1 >= V) wn1 = V-1;
  const float* Wp0 = W + (size_t)wn0*DEC + kq;
  const float* Wp1 = W + (size_t)wn1*DEC + kq;
  float4 a=*(const float4*)Ap, w0=*(const float4*)Wp0, w1=*(const float4*)Wp1;
  float acc[8][4];
  #pragma unroll
  for (int j=0;j<8;j++){ acc[j][0]=acc[j][1]=acc[j][2]=acc[j][3]=0.f; }
  for (int k0=0;k0<DEC;k0+=16){
    sA[lr*17+kq+0]=f2tf(a.x); sA[lr*17+kq+1]=f2tf(a.y); sA[lr*17+kq+2]=f2tf(a.z); sA[lr*17+kq+3]=f2tf(a.w);
    sW[lr*17+kq+0]=f2tf(w0.x); sW[lr*17+kq+1]=f2tf(w0.y); sW[lr*17+kq+2]=f2tf(w0.z); sW[lr*17+kq+3]=f2tf(w0.w);
    sW[(lr+64)*17+kq+0]=f2tf(w1.x); sW[(lr+64)*17+kq+1]=f2tf(w1.y); sW[(lr+64)*17+kq+2]=f2tf(w1.z); sW[(lr+64)*17+kq+3]=f2tf(w1.w);
    __syncthreads();
    if (k0+16<DEC){
      a=*(const float4*)(Ap+k0+16); w0=*(const float4*)(Wp0+k0+16); w1=*(const float4*)(Wp1+k0+16);
    }
    #pragma unroll
    for (int kk=0;kk<16;kk+=8){
      uint32_t af[4];
      int r=mr*16+(lane>>2), c=kk+(lane&3);
      af[0]=sA[r*17+c]; af[1]=sA[(r+8)*17+c]; af[2]=sA[r*17+c+4]; af[3]=sA[(r+8)*17+c+4];
      #pragma unroll
      for (int j=0;j<8;j++){
        int n=nc*64+j*8+(lane>>2);
        uint32_t bf[2]={ sW[n*17+c], sW[n*17+c+4] };
        mma_tf32(acc[j], af, bf);
      }
    }
    __syncthreads();
  }
  int r0=mr*16+(lane>>2), c0=(lane&3)*2;
  bool a0 = r0 < nact, a1 = (r0+8) < nact;
  float* row0 = preds + (size_t)r0*TSTEPS*V + (size_t)t*V;
  float* row1 = preds + (size_t)(r0+8)*TSTEPS*V + (size_t)t*V;
  #pragma unroll
  for (int j=0;j<8;j++){
    int gn=gn0+nc*64+j*8+c0;
    if (gn < V){
      row0[gn] = a0 ? (acc[j][0]+bias[gn]) : 0.f;
      row1[gn] = a1 ? (acc[j][2]+bias[gn]) : 0.f;
    }
    if (gn+1 < V){
      row0[gn+1] = a0 ? (acc[j][1]+bias[gn+1]) : 0.f;
      row1[gn+1] = a1 ? (acc[j][3]+bias[gn+1]) : 0.f;
    }
  }
}

// hproj (fp32 FFMA — recurrence-critical): BM=64 BN=128 BK=32
__device__ __forceinline__ void hproj_dev(float* sbuf, int gn0, int t,
    const float* __restrict__ Wda, const float* __restrict__ Wbeta, const float* __restrict__ Whh){
  float* sA = sbuf;            // [32][68]
  float* sW = sbuf + 32*68;    // [32][132]
  int tid=threadIdx.x, tx=tid&15, ty=tid>>4;
  int nact = g_bact[t];
  bool act = (ty*4 < nact);
  const float* Wp; float* Cp; int cs, coff;
  if (gn0 < ATT)          { Wp = Wda   + (size_t)gn0*DEC;           Cp = g_att2;    cs = ATT; coff = gn0; }
  else if (gn0 < ATT+ENC) { Wp = Wbeta + (size_t)(gn0-ATT)*DEC;     Cp = g_gatepre; cs = ENC; coff = gn0-ATT; }
  else                    { Wp = Whh   + (size_t)(gn0-ATT-ENC)*DEC; Cp = g_gates;   cs = G4;  coff = gn0-ATT-ENC; }
  int rA0 = tid>>3,        kqA0 = tid&7;
  int rA1 = (tid+256)>>3,  kqA1 = (tid+256)&7;
  const float* ApA0 = g_h + rA0*DEC + kqA0*4;
  const float* ApA1 = g_h + rA1*DEC + kqA1*4;
  int rW = tid>>3, kqW = tid&7;
  float4 pa0=*(const float4*)ApA0, pa1=*(const float4*)ApA1;
  float4 pw[4];
  #pragma unroll
  for (int i=0;i<4;i++) pw[i] = *(const float4*)(Wp + (size_t)(rW + i*32)*DEC + kqW*4);
  float acc[4][8]={};
  for (int k0=0;k0<DEC;k0+=32){
    sA[(kqA0*4+0)*68+rA0]=pa0.x; sA[(kqA0*4+1)*68+rA0]=pa0.y; sA[(kqA0*4+2)*68+rA0]=pa0.z; sA[(kqA0*4+3)*68+rA0]=pa0.w;
    sA[(kqA1*4+0)*68+rA1]=pa1.x; sA[(kqA1*4+1)*68+rA1]=pa1.y; sA[(kqA1*4+2)*68+rA1]=pa1.z; sA[(kqA1*4+3)*68+rA1]=pa1.w;
    #pragma unroll
    for (int i=0;i<4;i++){
      int n = rW + i*32;
      sW[(kqW*4+0)*132+n]=pw[i].x; sW[(kqW*4+1)*132+n]=pw[i].y; sW[(kqW*4+2)*132+n]=pw[i].z; sW[(kqW*4+3)*132+n]=pw[i].w;
    }
    __syncthreads();
    if (k0+32<DEC){
      pa0=*(const float4*)(ApA0+k0+32); pa1=*(const float4*)(ApA1+k0+32);
      #pragma unroll
      for (int i=0;i<4;i++) pw[i] = *(const float4*)(Wp + (size_t)(rW + i*32)*DEC + kqW*4 + k0+32);
    }
    if (act){
      #pragma unroll
      for (int k=0;k<32;k++){
        float4 a=*(const float4*)&sA[k*68+ty*4];
        float4 ya=*(const float4*)&sW[k*132+tx*8];
        float4 yb=*(const float4*)&sW[k*132+tx*8+4];
        float av[4]={a.x,a.y,a.z,a.w};
        float wv[8]={ya.x,ya.y,ya.z,ya.w,yb.x,yb.y,yb.z,yb.w};
        #pragma unroll
        for (int i=0;i<4;i++)
          #pragma unroll
          for (int j=0;j<8;j++)
            acc[i][j] += av[i]*wv[j];
      }
    }
    __syncthreads();
  }
  if (act){
    #pragma unroll
    for (int i=0;i<4;i++){
      int m = ty*4+i;
      if (m < nact){
        *(float4*)(Cp + (size_t)m*cs + coff + tx*8)     = make_float4(acc[i][0],acc[i][1],acc[i][2],acc[i][3]);
        *(float4*)(Cp + (size_t)m*cs + coff + tx*8 + 4) = make_float4(acc[i][4],acc[i][5],acc[i][6],acc[i][7]);
      }
    }
  }
}

// merged: blocks [0,FCBLK) do fc(t-1) on tensor cores; rest do hproj(t) fp32
__global__ void __launch_bounds__(256) k_fc_hproj(
    const float* __restrict__ fcW, const float* __restrict__ fcb, float* __restrict__ preds,
    const float* __restrict__ Wda, const float* __restrict__ Wbeta, const float* __restrict__ Whh,
    int t){
  __shared__ __align__(16) uint32_t sbuf[32*68 + 32*132];
  if ((int)blockIdx.x < FCBLK) fc_tc_dev(sbuf, blockIdx.x*128, t-1, fcW, fcb, preds);
  else                         hproj_dev((float*)sbuf, (blockIdx.x-FCBLK)*128, t, Wda, Wbeta, Whh);
}
__global__ void __launch_bounds__(256) k_hproj_only(
    const float* __restrict__ Wda, const float* __restrict__ Wbeta, const float* __restrict__ Whh, int t){
  __shared__ __align__(16) float sbuf[32*68 + 32*132];
  hproj_dev(sbuf, blockIdx.x*128, t, Wda, Wbeta, Whh);
}
__global__ void __launch_bounds__(256) k_fc_only(
    const float* __restrict__ fcW, const float* __restrict__ fcb, float* __restrict__ preds, int t){
  __shared__ __align__(16) uint32_t sbuf[64*17 + 128*17];
  fc_tc_dev(sbuf, blockIdx.x*128, t, fcW, fcb, preds);
}

// per-step: e -> softmax -> alphas, + embedding gather
__global__ void k_alpha(const float* __restrict__ b_dec_att, const float* __restrict__ w_full,
                        const float* __restrict__ b_full, const float* __restrict__ emb_table,
                        const int* __restrict__ caps, float* __restrict__ alphas, int t){
  int b = blockIdx.x, tid = threadIdx.x;
  int nact = g_bact[t];
  if (b >= nact){
    for (int p=tid;p<PP;p+=256) alphas[(size_t)b*TSTEPS*PP + (size_t)t*PP + p] = 0.f;
    return;
  }
  __shared__ float s_a2[ATT];
  __shared__ float s_wf[ATT];
  __shared__ float s_e[PP];
  __shared__ float s_red[8];
  for (int a=tid;a<ATT;a+=256){
    s_a2[a] = g_att2[b*ATT + a] + b_dec_att[a];
    s_wf[a] = w_full[a];
  }
  __syncthreads();
  int warp = tid>>5, lane = tid&31;
  const float* a1 = g_att1 + (size_t)b*PP*ATT;
  float bf = b_full[0];
  for (int p=warp; p<PP; p+=8){
    const float* r = a1 + (size_t)p*ATT;
    float s=0.f;
    #pragma unroll 4
    for (int a=lane; a<ATT; a+=32)
      s += fmaxf(r[a]+s_a2[a],0.f)*s_wf[a];
    #pragma unroll
    for (int o=16;o;o>>=1) s += __shfl_xor_sync(0xffffffffu,s,o);
    if (lane==0) s_e[p] = s + bf;
  }
  __syncthreads();
  float m = -1e30f;
  for (int p=tid;p<PP;p+=256) m = fmaxf(m, s_e[p]);
  #pragma unroll
  for (int o=16;o;o>>=1) m = fmaxf(m,__shfl_xor_sync(0xffffffffu,m,o));
  if (lane==0) s_red[warp]=m;
  __syncthreads();
  float mx = s_red[0];
  #pragma unroll
  for (int i=1;i<8;i++) mx = fmaxf(mx, s_red[i]);
  __syncthreads();
  float sum=0.f;
  for (int p=tid;p<PP;p+=256){ float ex=expf(s_e[p]-mx); s_e[p]=ex; sum+=ex; }
  #pragma unroll
  for (int o=16;o;o>>=1) sum += __shfl_xor_sync(0xffffffffu,sum,o);
  if (lane==0) s_red[warp]=sum;
  __syncthreads();
  float tot = 0.f;
  #pragma unroll
  for (int i=0;i<8;i++) tot += s_red[i];
  float inv = 1.0f/tot;
  for (int p=tid;p<PP;p+=256)
    alphas[(size_t)b*TSTEPS*PP + (size_t)t*PP + p] = s_e[p]*inv;
  int tok = caps[b*LCAP + t];
  for (int jj=tid;jj<EMB;jj+=256)
    g_x[b*XDIM + jj] = emb_table[(size_t)tok*EMB + jj];
}

// per-step: awe + gate -> g_x[:, EMB:]
__global__ void k_awe(const float* __restrict__ b_beta, const float* __restrict__ alphas, int t){
  int b = blockIdx.x;
  if (b >= g_bact[t]) return;
  int tid = threadIdx.x;
  __shared__ float s_al[PP];
  const float* ap = alphas + (size_t)b*TSTEPS*PP + (size_t)t*PP;
  for (int p=tid;p<PP;p+=256) s_al[p] = ap[p];
  __syncthreads();
  int e2 = blockIdx.y*256 + tid;
  const __half2* eb = (const __half2*)g_ench + (size_t)b*PP*(ENC/2) + e2;
  float ax=0.f, ay=0.f, bx=0.f, by=0.f;
  #pragma unroll 1
  for (int p=0;p<PP;p+=4){
    float2 f0 = __half22float2(eb[(size_t) p   *(ENC/2)]);
    float2 f1 = __half22float2(eb[(size_t)(p+1)*(ENC/2)]);
    float2 f2 = __half22float2(eb[(size_t)(p+2)*(ENC/2)]);
    float2 f3 = __half22float2(eb[(size_t)(p+3)*(ENC/2)]);
    ax += s_al[p]*f0.x   + s_al[p+1]*f1.x;
    ay += s_al[p]*f0.y   + s_al[p+1]*f1.y;
    bx += s_al[p+2]*f2.x + s_al[p+3]*f3.x;
    by += s_al[p+2]*f2.y + s_al[p+3]*f3.y;
  }
  int e = e2*2;
  float g0 = sigmoidf_(g_gatepre[b*ENC+e]   + b_beta[e]);
  float g1 = sigmoidf_(g_gatepre[b*ENC+e+1] + b_beta[e+1]);
  *(float2*)(g_x + (size_t)b*XDIM + EMB + e) = make_float2(g0*(ax+bx), g1*(ay+by));
}

// per-step: split-K partials of x @ W_ih^T (fp32 FFMA — recurrence-critical)
__global__ void __launch_bounds__(256) k_gates(const float* __restrict__ Wih, int t){
  __shared__ __align__(16) float sbuf[32*68 + 32*132];
  float* sA = sbuf;
  float* sW = sbuf + 32*68;
  int tid=threadIdx.x, tx=tid&15, ty=tid>>4;
  int gn0 = blockIdx.x*128;
  int kbase = blockIdx.z*KSLICE;
  int nact = g_bact[t];
  bool act = (ty*4 < nact);
  int rA0 = tid>>3,        kqA0 = tid&7;
  int rA1 = (tid+256)>>3,  kqA1 = (tid+256)&7;
  const float* ApA0 = g_x + (size_t)rA0*XDIM + kbase + kqA0*4;
  const float* ApA1 = g_x + (size_t)rA1*XDIM + kbase + kqA1*4;
  int rW = tid>>3, kqW = tid&7;
  const float* Wp = Wih + (size_t)gn0*XDIM + kbase;
  float4 pa0=*(const float4*)ApA0, pa1=*(const float4*)ApA1;
  float4 pw[4];
  #pragma unroll
  for (int i=0;i<4;i++) pw[i] = *(const float4*)(Wp + (size_t)(rW + i*32)*XDIM + kqW*4);
  float acc[4][8]={};
  for (int k0=0;k0<KSLICE;k0+=32){
    sA[(kqA0*4+0)*68+rA0]=pa0.x; sA[(kqA0*4+1)*68+rA0]=pa0.y; sA[(kqA0*4+2)*68+rA0]=pa0.z; sA[(kqA0*4+3)*68+rA0]=pa0.w;
    sA[(kqA1*4+0)*68+rA1]=pa1.x; sA[(kqA1*4+1)*68+rA1]=pa1.y; sA[(kqA1*4+2)*68+rA1]=pa1.z; sA[(kqA1*4+3)*68+rA1]=pa1.w;
    #pragma unroll
    for (int i=0;i<4;i++){
      int n = rW + i*32;
      sW[(kqW*4+0)*132+n]=pw[i].x; sW[(kqW*4+1)*132+n]=pw[i].y; sW[(kqW*4+2)*132+n]=pw[i].z; sW[(kqW*4+3)*132+n]=pw[i].w;
    }
    __syncthreads();
    if (k0+32<KSLICE){
      pa0=*(const float4*)(ApA0+k0+32); pa1=*(const float4*)(ApA1+k0+32);
      #pragma unroll
      for (int i=0;i<4;i++) pw[i] = *(const float4*)(Wp + (size_t)(rW + i*32)*XDIM + kqW*4 + k0+32);
    }
    if (act){
      #pragma unroll
      for (int k=0;k<32;k++){
        float4 a=*(const float4*)&sA[k*68+ty*4];
        float4 ya=*(const float4*)&sW[k*132+tx*8];
        float4 yb=*(const float4*)&sW[k*132+tx*8+4];
        float av[4]={a.x,a.y,a.z,a.w};
        float wv[8]={ya.x,ya.y,ya.z,ya.w,yb.x,yb.y,yb.z,yb.w};
        #pragma unroll
        for (int i=0;i<4;i++)
          #pragma unroll
          for (int j=0;j<8;j++)
            acc[i][j] += av[i]*wv[j];
      }
    }
    __syncthreads();
  }
  if (act){
    float* outp = g_gpart + (size_t)blockIdx.z*B*G4;
    #pragma unroll
    for (int i=0;i<4;i++){
      int mm = ty*4+i;
      if (mm < nact){
        *(float4*)(outp + (size_t)mm*G4 + gn0 + tx*8)     = make_float4(acc[i][0],acc[i][1],acc[i][2],acc[i][3]);
        *(float4*)(outp + (size_t)mm*G4 + gn0 + tx*8 + 4) = make_float4(acc[i][4],acc[i][5],acc[i][6],acc[i][7]);
      }
    }
  }
}

// per-step LSTM pointwise
__global__ void k_lstm(const float* __restrict__ b_ih, const float* __restrict__ b_hh, int t){
  int b = blockIdx.x;
  if (b >= g_bact[t]) return;
  int j = threadIdx.x;
  const size_t S = (size_t)B*G4;
  int base = b*G4;
  float g[4];
  #pragma unroll
  for (int q=0;q<4;q++){
    int off = base + q*DEC + j;
    float v = g_gates[off] + b_ih[q*DEC+j] + b_hh[q*DEC+j];
    #pragma unroll
    for (int s=0;s<NSLICE;s++) v += g_gpart[(size_t)s*S + off];
    g[q] = v;
  }
  float cn = sigmoidf_(g[1])*g_c[b*DEC+j] + sigmoidf_(g[0])*tanhf(g[2]);
  float hn = sigmoidf_(g[3])*tanhf(cn);
  g_c[b*DEC+j]=cn; g_h[b*DEC+j]=hn;
}

// ---------------- launch ----------------
extern "C" void kernel_launch(void* const* d_in, const int* in_sizes, int n_in,
                              void* d_out, int out_size){
  (void)in_sizes; (void)n_in; (void)out_size;
  const float* enc       = (const float*)d_in[0];
  const int*   caps      = (const int*)  d_in[1];
  const int*   caplen    = (const int*)  d_in[2];
  const float* emb_table = (const float*)d_in[3];
  const float* W_enc_att = (const float*)d_in[4];
  const float* b_enc_att = (const float*)d_in[5];
  const float* W_dec_att = (const float*)d_in[6];
  const float* b_dec_att = (const float*)d_in[7];
  const float* w_full    = (const float*)d_in[8];
  const float* b_full    = (const float*)d_in[9];
  const float* W_init_h  = (const float*)d_in[10];
  const float* b_init_h  = (const float*)d_in[11];
  const float* W_init_c  = (const float*)d_in[12];
  const float* b_init_c  = (const float*)d_in[13];
  const float* W_beta    = (const float*)d_in[14];
  const float* b_beta    = (const float*)d_in[15];
  const float* W_ih      = (const float*)d_in[16];
  const float* b_ih      = (const float*)d_in[17];
  const float* W_hh      = (const float*)d_in[18];
  const float* b_hh      = (const float*)d_in[19];
  const float* fc_W      = (const float*)d_in[20];
  const float* fc_b      = (const float*)d_in[21];

  float* preds  = (float*)d_out;                       // [B, T, V]
  float* alphas = preds + (size_t)B*TSTEPS*V;          // [B, T, P]

  k_bact<<<1, 32>>>(caplen);
  k_cvt<<<(int)(((size_t)B*PP*ENC/4 + 255)/256), 256>>>(enc);
  k_mean<<<dim3(B, ENC/256), 256>>>(enc);
  k_init<<<dim3(32,1,4), 256>>>(W_init_h, W_init_c);
  k_init_red<<<64, 256>>>(b_init_h, b_init_c);
  k_att1_tc<<<dim3(ATT/128, (B*PP)/64), 256>>>(enc, W_enc_att, b_enc_att);

  for (int t=0; t<TSTEPS; t++){
    if (t == 0)
      k_hproj_only<<<HPBLK, 256>>>(W_dec_att, W_beta, W_hh, t);
    else
      k_fc_hproj<<<FCBLK+HPBLK, 256>>>(fc_W, fc_b, preds, W_dec_att, W_beta, W_hh, t);
    k_alpha<<<B, 256>>>(b_dec_att, w_full, b_full, emb_table, caps, alphas, t);
    k_awe  <<<dim3(B, ENC/512), 256>>>(b_beta, alphas, t);
    k_gates<<<dim3(G4/128, 1, NSLICE), 256>>>(W_ih, t);
    k_lstm <<<B, DEC>>>(b_ih, b_hh, t);
  }
  k_fc_only<<<FCBLK, 256>>>(fc_W, fc_b, preds, TSTEPS-1);
}

// round 5
// speedup vs baseline: 2.4972x; 1.1412x over previous
#include <cuda_runtime.h>
#include <cuda_fp16.h>
#include <cstdint>

#define B      64
#define PP     196
#define ENC    2048
#define LCAP   32
#define V      20000
#define ATT    512
#define EMB    512
#define DEC    512
#define TSTEPS 31
#define XDIM   (EMB+ENC)   /* 2560 */
#define G4     (4*DEC)     /* 2048 */
#define NSLICE 8
#define KSLICE (ENC/NSLICE) /* 256: gates K is now the awe part only */
#define FCBLK  157          /* ceil(20000/128) */
#define HPBLK  ((ATT+ENC+G4)/128) /* 36 */

// ---------------- device scratch ----------------
__device__ __half g_att1h[(size_t)B*PP*ATT];   // fp16 att1 (+bias)
__device__ __half g_ench[(size_t)B*PP*ENC];    // fp16 encoder_out
__device__ __half g_fcWh[(size_t)V*DEC];       // fp16 fc_W
__device__ float  g_mean[B*ENC];
__device__ float  g_h[B*DEC];
__device__ float  g_c[B*DEC];
__device__ float  g_att2[B*ATT];
__device__ float  g_gatepre[B*ENC];
__device__ float  g_gates[B*G4];               // h @ W_hh^T
__device__ float  g_gpart[(size_t)NSLICE*B*G4];
__device__ float  g_eg[(size_t)B*TSTEPS*G4];   // precomputed emb @ W_ih[:, :512]^T
__device__ float  g_xe[B*ENC];                 // gate * awe
__device__ float  g_ipart[4*64*1024];
__device__ int    g_bact[TSTEPS];

__device__ __forceinline__ float sigmoidf_(float x){ return 1.0f/(1.0f+expf(-x)); }
__device__ __forceinline__ uint32_t f2tf(float f){
  uint32_t u; asm("cvt.rna.tf32.f32 %0, %1;" : "=r"(u) : "f"(f)); return u;
}
__device__ __forceinline__ void mma_tf32(float* d, const uint32_t* a, const uint32_t* b){
  asm volatile("mma.sync.aligned.m16n8k8.row.col.f32.tf32.tf32.f32 "
    "{%0,%1,%2,%3},{%4,%5,%6,%7},{%8,%9},{%0,%1,%2,%3};"
    : "+f"(d[0]),"+f"(d[1]),"+f"(d[2]),"+f"(d[3])
    : "r"(a[0]),"r"(a[1]),"r"(a[2]),"r"(a[3]),"r"(b[0]),"r"(b[1]));
}

// ---------------- one-time kernels ----------------
__global__ void k_bact(const int* __restrict__ caplen){
  int t = threadIdx.x;
  if (t < TSTEPS){
    int c = 0;
    for (int b=0;b<B;b++) c += ((caplen[b]-1) > t) ? 1 : 0;
    g_bact[t] = c;
  }
}

// fused: encoder fp16 copy + mean over P
__global__ void k_cvtmean(const float* __restrict__ enc){
  int b = blockIdx.x;
  int e = blockIdx.y*256 + threadIdx.x;
  const float* p0 = enc + (size_t)b*PP*ENC + e;
  __half* h0 = g_ench + (size_t)b*PP*ENC + e;
  float s = 0.f;
  #pragma unroll 4
  for (int p=0;p<PP;p++){
    float v = p0[(size_t)p*ENC];
    s += v;
    h0[(size_t)p*ENC] = __float2half_rn(v);
  }
  g_mean[b*ENC + e] = s * (1.0f/PP);
}

__global__ void k_cvtfcw(const float* __restrict__ W){
  size_t i = (size_t)blockIdx.x*blockDim.x + threadIdx.x;
  const size_t n4 = (size_t)V*DEC/4;
  if (i >= n4) return;
  float4 v = ((const float4*)W)[i];
  __half2* o = (__half2*)g_fcWh;
  o[i*2]   = __floats2half2_rn(v.x, v.y);
  o[i*2+1] = __floats2half2_rn(v.z, v.w);
}

// init h0/c0 split-K partials, grid (32,1,4)
__global__ void k_init(const float* __restrict__ Wh, const float* __restrict__ Wc){
  __shared__ float sA[32][68];
  __shared__ float sW[32][34];
  int tid = threadIdx.x, tx = tid & 15, ty = tid >> 4;
  int gn0 = blockIdx.x * 32;
  int ks  = blockIdx.z;
  const float* Wp = (gn0 < DEC) ? (Wh + (size_t)gn0*ENC) : (Wc + (size_t)(gn0-DEC)*ENC);
  float acc[4][2] = {};
  for (int k0=ks*512; k0<ks*512+512; k0+=32){
    #pragma unroll
    for (int i=0;i<2;i++){
      int lin = tid + i*256, row = lin >> 3, kq = lin & 7;
      float4 v = *(const float4*)(g_mean + row*ENC + k0 + kq*4);
      sA[kq*4+0][row]=v.x; sA[kq*4+1][row]=v.y; sA[kq*4+2][row]=v.z; sA[kq*4+3][row]=v.w;
    }
    {
      int n = tid >> 3, kq = tid & 7;
      float4 v = *(const float4*)(Wp + (size_t)n*ENC + k0 + kq*4);
      sW[kq*4+0][n]=v.x; sW[kq*4+1][n]=v.y; sW[kq*4+2][n]=v.z; sW[kq*4+3][n]=v.w;
    }
    __syncthreads();
    #pragma unroll
    for (int k=0;k<32;k++){
      float4 a = *(const float4*)&sA[k][ty*4];
      float2 w = *(const float2*)&sW[k][tx*2];
      acc[0][0]+=a.x*w.x; acc[0][1]+=a.x*w.y;
      acc[1][0]+=a.y*w.x; acc[1][1]+=a.y*w.y;
      acc[2][0]+=a.z*w.x; acc[2][1]+=a.z*w.y;
      acc[3][0]+=a.w*w.x; acc[3][1]+=a.w*w.y;
    }
    __syncthreads();
  }
  #pragma unroll
  for (int i=0;i<4;i++){
    int m = ty*4+i;
    #pragma unroll
    for (int j=0;j<2;j++)
      g_ipart[(size_t)ks*64*1024 + m*1024 + gn0 + tx*2 + j] = acc[i][j];
  }
}

__global__ void k_init_red(const float* __restrict__ bh, const float* __restrict__ bc){
  int m = blockIdx.x;
  for (int c=threadIdx.x; c<1024; c+=256){
    float v = g_ipart[m*1024+c] + g_ipart[64*1024 + m*1024+c]
            + g_ipart[2*64*1024 + m*1024+c] + g_ipart[3*64*1024 + m*1024+c];
    if (c < DEC) g_h[m*DEC + c]       = v + bh[c];
    else         g_c[m*DEC + (c-DEC)] = v + bc[c-DEC];
  }
}

// att1 via tf32 tensor cores, epilogue stores fp16
__global__ void __launch_bounds__(256) k_att1_tc(const float* __restrict__ A,
                                                 const float* __restrict__ W,
                                                 const float* __restrict__ bias){
  __shared__ uint32_t sA[64*17];
  __shared__ uint32_t sW[128*17];
  int tid=threadIdx.x, lane=tid&31, wp=tid>>5;
  int mr=wp>>1, nc=wp&1;
  int m0=blockIdx.y*64, gn0=blockIdx.x*128;
  int lr=tid>>2, kq=(tid&3)*4;
  const float* Ap  = A + (size_t)(m0+lr)*ENC + kq;
  const float* Wp0 = W + (size_t)(gn0+lr)*ENC + kq;
  const float* Wp1 = W + (size_t)(gn0+lr+64)*ENC + kq;
  float4 a=*(const float4*)Ap, w0=*(const float4*)Wp0, w1=*(const float4*)Wp1;
  float acc[8][4];
  #pragma unroll
  for (int j=0;j<8;j++){ acc[j][0]=acc[j][1]=acc[j][2]=acc[j][3]=0.f; }
  for (int k0=0;k0<ENC;k0+=16){
    sA[lr*17+kq+0]=f2tf(a.x); sA[lr*17+kq+1]=f2tf(a.y); sA[lr*17+kq+2]=f2tf(a.z); sA[lr*17+kq+3]=f2tf(a.w);
    sW[lr*17+kq+0]=f2tf(w0.x); sW[lr*17+kq+1]=f2tf(w0.y); sW[lr*17+kq+2]=f2tf(w0.z); sW[lr*17+kq+3]=f2tf(w0.w);
    sW[(lr+64)*17+kq+0]=f2tf(w1.x); sW[(lr+64)*17+kq+1]=f2tf(w1.y); sW[(lr+64)*17+kq+2]=f2tf(w1.z); sW[(lr+64)*17+kq+3]=f2tf(w1.w);
    __syncthreads();
    if (k0+16<ENC){
      a=*(const float4*)(Ap+k0+16); w0=*(const float4*)(Wp0+k0+16); w1=*(const float4*)(Wp1+k0+16);
    }
    #pragma unroll
    for (int kk=0;kk<16;kk+=8){
      uint32_t af[4];
      int r=mr*16+(lane>>2), c=kk+(lane&3);
      af[0]=sA[r*17+c]; af[1]=sA[(r+8)*17+c]; af[2]=sA[r*17+c+4]; af[3]=sA[(r+8)*17+c+4];
      #pragma unroll
      for (int j=0;j<8;j++){
        int n=nc*64+j*8+(lane>>2);
        uint32_t bf[2]={ sW[n*17+c], sW[n*17+c+4] };
        mma_tf32(acc[j], af, bf);
      }
    }
    __syncthreads();
  }
  int r0=m0+mr*16+(lane>>2), c0=(lane&3)*2;
  #pragma unroll
  for (int j=0;j<8;j++){
    int gn=gn0+nc*64+j*8+c0;
    *(__half2*)(g_att1h + (size_t)r0*ATT + gn)     = __floats2half2_rn(acc[j][0]+bias[gn], acc[j][1]+bias[gn+1]);
    *(__half2*)(g_att1h + (size_t)(r0+8)*ATT + gn) = __floats2half2_rn(acc[j][2]+bias[gn], acc[j][3]+bias[gn+1]);
  }
}

// one-time: g_eg[b,t,:] = emb_table[caps[b,t]] @ W_ih[:, :512]^T  (exact fp32)
// grid (G4/128, 1984/64); BM=64 BN=128 BK=32
__global__ void __launch_bounds__(256) k_embgate(const float* __restrict__ emb_table,
                                                 const int* __restrict__ caps,
                                                 const float* __restrict__ Wih){
  __shared__ __align__(16) float sbuf[32*68 + 32*132];
  float* sA = sbuf;
  float* sW = sbuf + 32*68;
  int tid=threadIdx.x, tx=tid&15, ty=tid>>4;
  int gn0 = blockIdx.x*128;
  int m0  = blockIdx.y*64;
  int rA0 = tid>>3,        kqA0 = tid&7;
  int rA1 = (tid+256)>>3,  kqA1 = (tid+256)&7;
  int gr0 = m0+rA0, gr1 = m0+rA1;
  int tok0 = caps[(gr0/TSTEPS)*LCAP + (gr0%TSTEPS)];
  int tok1 = caps[(gr1/TSTEPS)*LCAP + (gr1%TSTEPS)];
  const float* ApA0 = emb_table + (size_t)tok0*EMB + kqA0*4;
  const float* ApA1 = emb_table + (size_t)tok1*EMB + kqA1*4;
  int rW = tid>>3, kqW = tid&7;
  const float* Wp = Wih + (size_t)gn0*XDIM;   // emb part = cols [0,512)
  float4 pa0=*(const float4*)ApA0, pa1=*(const float4*)ApA1;
  float4 pw[4];
  #pragma unroll
  for (int i=0;i<4;i++) pw[i] = *(const float4*)(Wp + (size_t)(rW + i*32)*XDIM + kqW*4);
  float acc[4][8]={};
  for (int k0=0;k0<EMB;k0+=32){
    sA[(kqA0*4+0)*68+rA0]=pa0.x; sA[(kqA0*4+1)*68+rA0]=pa0.y; sA[(kqA0*4+2)*68+rA0]=pa0.z; sA[(kqA0*4+3)*68+rA0]=pa0.w;
    sA[(kqA1*4+0)*68+rA1]=pa1.x; sA[(kqA1*4+1)*68+rA1]=pa1.y; sA[(kqA1*4+2)*68+rA1]=pa1.z; sA[(kqA1*4+3)*68+rA1]=pa1.w;
    #pragma unroll
    for (int i=0;i<4;i++){
      int n = rW + i*32;
      sW[(kqW*4+0)*132+n]=pw[i].x; sW[(kqW*4+1)*132+n]=pw[i].y; sW[(kqW*4+2)*132+n]=pw[i].z; sW[(kqW*4+3)*132+n]=pw[i].w;
    }
    __syncthreads();
    if (k0+32<EMB){
      pa0=*(const float4*)(ApA0+k0+32); pa1=*(const float4*)(ApA1+k0+32);
      #pragma unroll
      for (int i=0;i<4;i++) pw[i] = *(const float4*)(Wp + (size_t)(rW + i*32)*XDIM + kqW*4 + k0+32);
    }
    #pragma unroll
    for (int k=0;k<32;k++){
      float4 a=*(const float4*)&sA[k*68+ty*4];
      float4 ya=*(const float4*)&sW[k*132+tx*8];
      float4 yb=*(const float4*)&sW[k*132+tx*8+4];
      float av[4]={a.x,a.y,a.z,a.w};
      float wv[8]={ya.x,ya.y,ya.z,ya.w,yb.x,yb.y,yb.z,yb.w};
      #pragma unroll
      for (int i=0;i<4;i++)
        #pragma unroll
        for (int j=0;j<8;j++)
          acc[i][j] += av[i]*wv[j];
    }
    __syncthreads();
  }
  #pragma unroll
  for (int i=0;i<4;i++){
    int r = m0 + ty*4 + i;
    *(float4*)(g_eg + (size_t)r*G4 + gn0 + tx*8)     = make_float4(acc[i][0],acc[i][1],acc[i][2],acc[i][3]);
    *(float4*)(g_eg + (size_t)r*G4 + gn0 + tx*8 + 4) = make_float4(acc[i][4],acc[i][5],acc[i][6],acc[i][7]);
  }
}

// fc via tf32 tensor cores, fp16 weights
__device__ __forceinline__ void fc_tc_dev(uint32_t* sbuf, int gn0, int t,
    const float* __restrict__ bias, float* __restrict__ preds){
  uint32_t* sA = sbuf;
  uint32_t* sW = sbuf + 64*17;
  int tid=threadIdx.x, lane=tid&31, wp=tid>>5;
  int mr=wp>>1, nc=wp&1;
  int nact = g_bact[t];
  int lr=tid>>2, kq=(tid&3)*4;
  const float* Ap = g_h + lr*DEC + kq;
  int wn0 = gn0 + lr;      if (wn0 >= V) wn0 = V-1;
  int wn1 = gn0 + lr + 64; if (wn1 >= V) wn1 = V-1;
  const __half* Wp0 = g_fcWh + (size_t)wn0*DEC + kq;
  const __half* Wp1 = g_fcWh + (size_t)wn1*DEC + kq;
  float4 a=*(const float4*)Ap;
  __half2 h0a=*(const __half2*)Wp0, h0b=*(const __half2*)(Wp0+2);
  __half2 h1a=*(const __half2*)Wp1, h1b=*(const __half2*)(Wp1+2);
  float acc[8][4];
  #pragma unroll
  for (int j=0;j<8;j++){ acc[j][0]=acc[j][1]=acc[j][2]=acc[j][3]=0.f; }
  for (int k0=0;k0<DEC;k0+=16){
    sA[lr*17+kq+0]=f2tf(a.x); sA[lr*17+kq+1]=f2tf(a.y); sA[lr*17+kq+2]=f2tf(a.z); sA[lr*17+kq+3]=f2tf(a.w);
    sW[lr*17+kq+0]=f2tf(__low2float(h0a));  sW[lr*17+kq+1]=f2tf(__high2float(h0a));
    sW[lr*17+kq+2]=f2tf(__low2float(h0b));  sW[lr*17+kq+3]=f2tf(__high2float(h0b));
    sW[(lr+64)*17+kq+0]=f2tf(__low2float(h1a)); sW[(lr+64)*17+kq+1]=f2tf(__high2float(h1a));
    sW[(lr+64)*17+kq+2]=f2tf(__low2float(h1b)); sW[(lr+64)*17+kq+3]=f2tf(__high2float(h1b));
    __syncthreads();
    if (k0+16<DEC){
      a=*(const float4*)(Ap+k0+16);
      h0a=*(const __half2*)(Wp0+k0+16); h0b=*(const __half2*)(Wp0+k0+18);
      h1a=*(const __half2*)(Wp1+k0+16); h1b=*(const __half2*)(Wp1+k0+18);
    }
    #pragma unroll
    for (int kk=0;kk<16;kk+=8){
      uint32_t af[4];
      int r=mr*16+(lane>>2), c=kk+(lane&3);
      af[0]=sA[r*17+c]; af[1]=sA[(r+8)*17+c]; af[2]=sA[r*17+c+4]; af[3]=sA[(r+8)*17+c+4];
      #pragma unroll
      for (int j=0;j<8;j++){
        int n=nc*64+j*8+(lane>>2);
        uint32_t bf[2]={ sW[n*17+c], sW[n*17+c+4] };
        mma_tf32(acc[j], af, bf);
      }
    }
    __syncthreads();
  }
  int r0=mr*16+(lane>>2), c0=(lane&3)*2;
  bool a0 = r0 < nact, a1 = (r0+8) < nact;
  float* row0 = preds + (size_t)r0*TSTEPS*V + (size_t)t*V;
  float* row1 = preds + (size_t)(r0+8)*TSTEPS*V + (size_t)t*V;
  #pragma unroll
  for (int j=0;j<8;j++){
    int gn=gn0+nc*64+j*8+c0;
    if (gn < V){
      row0[gn] = a0 ? (acc[j][0]+bias[gn]) : 0.f;
      row1[gn] = a1 ? (acc[j][2]+bias[gn]) : 0.f;
    }
    if (gn+1 < V){
      row0[gn+1] = a0 ? (acc[j][1]+bias[gn+1]) : 0.f;
      row1[gn+1] = a1 ? (acc[j][3]+bias[gn+1]) : 0.f;
    }
  }
}

// hproj (fp32 — recurrence-critical)
__device__ __forceinline__ void hproj_dev(float* sbuf, int gn0, int t,
    const float* __restrict__ Wda, const float* __restrict__ Wbeta, const float* __restrict__ Whh){
  float* sA = sbuf;
  float* sW = sbuf + 32*68;
  int tid=threadIdx.x, tx=tid&15, ty=tid>>4;
  int nact = g_bact[t];
  bool act = (ty*4 < nact);
  const float* Wp; float* Cp; int cs, coff;
  if (gn0 < ATT)          { Wp = Wda   + (size_t)gn0*DEC;           Cp = g_att2;    cs = ATT; coff = gn0; }
  else if (gn0 < ATT+ENC) { Wp = Wbeta + (size_t)(gn0-ATT)*DEC;     Cp = g_gatepre; cs = ENC; coff = gn0-ATT; }
  else                    { Wp = Whh   + (size_t)(gn0-ATT-ENC)*DEC; Cp = g_gates;   cs = G4;  coff = gn0-ATT-ENC; }
  int rA0 = tid>>3,        kqA0 = tid&7;
  int rA1 = (tid+256)>>3,  kqA1 = (tid+256)&7;
  const float* ApA0 = g_h + rA0*DEC + kqA0*4;
  const float* ApA1 = g_h + rA1*DEC + kqA1*4;
  int rW = tid>>3, kqW = tid&7;
  float4 pa0=*(const float4*)ApA0, pa1=*(const float4*)ApA1;
  float4 pw[4];
  #pragma unroll
  for (int i=0;i<4;i++) pw[i] = *(const float4*)(Wp + (size_t)(rW + i*32)*DEC + kqW*4);
  float acc[4][8]={};
  for (int k0=0;k0<DEC;k0+=32){
    sA[(kqA0*4+0)*68+rA0]=pa0.x; sA[(kqA0*4+1)*68+rA0]=pa0.y; sA[(kqA0*4+2)*68+rA0]=pa0.z; sA[(kqA0*4+3)*68+rA0]=pa0.w;
    sA[(kqA1*4+0)*68+rA1]=pa1.x; sA[(kqA1*4+1)*68+rA1]=pa1.y; sA[(kqA1*4+2)*68+rA1]=pa1.z; sA[(kqA1*4+3)*68+rA1]=pa1.w;
    #pragma unroll
    for (int i=0;i<4;i++){
      int n = rW + i*32;
      sW[(kqW*4+0)*132+n]=pw[i].x; sW[(kqW*4+1)*132+n]=pw[i].y; sW[(kqW*4+2)*132+n]=pw[i].z; sW[(kqW*4+3)*132+n]=pw[i].w;
    }
    __syncthreads();
    if (k0+32<DEC){
      pa0=*(const float4*)(ApA0+k0+32); pa1=*(const float4*)(ApA1+k0+32);
      #pragma unroll
      for (int i=0;i<4;i++) pw[i] = *(const float4*)(Wp + (size_t)(rW + i*32)*DEC + kqW*4 + k0+32);
    }
    if (act){
      #pragma unroll
      for (int k=0;k<32;k++){
        float4 a=*(const float4*)&sA[k*68+ty*4];
        float4 ya=*(const float4*)&sW[k*132+tx*8];
        float4 yb=*(const float4*)&sW[k*132+tx*8+4];
        float av[4]={a.x,a.y,a.z,a.w};
        float wv[8]={ya.x,ya.y,ya.z,ya.w,yb.x,yb.y,yb.z,yb.w};
        #pragma unroll
        for (int i=0;i<4;i++)
          #pragma unroll
          for (int j=0;j<8;j++)
            acc[i][j] += av[i]*wv[j];
      }
    }
    __syncthreads();
  }
  if (act){
    #pragma unroll
    for (int i=0;i<4;i++){
      int m = ty*4+i;
      if (m < nact){
        *(float4*)(Cp + (size_t)m*cs + coff + tx*8)     = make_float4(acc[i][0],acc[i][1],acc[i][2],acc[i][3]);
        *(float4*)(Cp + (size_t)m*cs + coff + tx*8 + 4) = make_float4(acc[i][4],acc[i][5],acc[i][6],acc[i][7]);
      }
    }
  }
}

__global__ void __launch_bounds__(256) k_fc_hproj(
    const float* __restrict__ fcb, float* __restrict__ preds,
    const float* __restrict__ Wda, const float* __restrict__ Wbeta, const float* __restrict__ Whh,
    int t){
  __shared__ __align__(16) uint32_t sbuf[32*68 + 32*132];
  if ((int)blockIdx.x < FCBLK) fc_tc_dev(sbuf, blockIdx.x*128, t-1, fcb, preds);
  else                         hproj_dev((float*)sbuf, (blockIdx.x-FCBLK)*128, t, Wda, Wbeta, Whh);
}
__global__ void __launch_bounds__(256) k_hproj_only(
    const float* __restrict__ Wda, const float* __restrict__ Wbeta, const float* __restrict__ Whh, int t){
  __shared__ __align__(16) float sbuf[32*68 + 32*132];
  hproj_dev(sbuf, blockIdx.x*128, t, Wda, Wbeta, Whh);
}
__global__ void __launch_bounds__(256) k_fc_only(
    const float* __restrict__ fcb, float* __restrict__ preds, int t){
  __shared__ __align__(16) uint32_t sbuf[64*17 + 128*17];
  fc_tc_dev(sbuf, blockIdx.x*128, t, fcb, preds);
}

// fused per-step attention: e -> softmax -> alphas -> awe -> gate*awe -> g_xe. 512 threads.
__global__ void __launch_bounds__(512) k_alpha_awe(
    const float* __restrict__ b_dec_att, const float* __restrict__ w_full,
    const float* __restrict__ b_full, const float* __restrict__ b_beta,
    float* __restrict__ alphas, int t){
  int b = blockIdx.x, tid = threadIdx.x;
  int nact = g_bact[t];
  if (b >= nact){
    for (int p=tid;p<PP;p+=512) alphas[(size_t)b*TSTEPS*PP + (size_t)t*PP + p] = 0.f;
    return;
  }
  __shared__ float s_a2[ATT];
  __shared__ float s_wf[ATT];
  __shared__ float s_e[PP];
  __shared__ float s_red[16];
  for (int a=tid;a<ATT;a+=512){
    s_a2[a] = g_att2[b*ATT + a] + b_dec_att[a];
    s_wf[a] = w_full[a];
  }
  __syncthreads();
  int warp = tid>>5, lane = tid&31;
  float bf = b_full[0];
  for (int p=warp; p<PP; p+=16){
    const __half2* r = (const __half2*)(g_att1h + (size_t)(b*PP+p)*ATT);
    float s=0.f;
    #pragma unroll
    for (int i=0;i<8;i++){
      int a2i = lane + i*32;
      float2 f = __half22float2(r[a2i]);
      int a = a2i*2;
      s += fmaxf(f.x + s_a2[a],0.f)*s_wf[a] + fmaxf(f.y + s_a2[a+1],0.f)*s_wf[a+1];
    }
    #pragma unroll
    for (int o=16;o;o>>=1) s += __shfl_xor_sync(0xffffffffu,s,o);
    if (lane==0) s_e[p] = s + bf;
  }
  __syncthreads();
  float m = (tid < PP) ? s_e[tid] : -1e30f;
  #pragma unroll
  for (int o=16;o;o>>=1) m = fmaxf(m,__shfl_xor_sync(0xffffffffu,m,o));
  if (lane==0) s_red[warp]=m;
  __syncthreads();
  float mx = s_red[0];
  #pragma unroll
  for (int i=1;i<16;i++) mx = fmaxf(mx, s_red[i]);
  __syncthreads();
  float sum = 0.f;
  if (tid < PP){ float ex = expf(s_e[tid]-mx); s_e[tid]=ex; sum=ex; }
  #pragma unroll
  for (int o=16;o;o>>=1) sum += __shfl_xor_sync(0xffffffffu,sum,o);
  if (lane==0) s_red[warp]=sum;
  __syncthreads();
  float tot = 0.f;
  #pragma unroll
  for (int i=0;i<16;i++) tot += s_red[i];
  float inv = 1.0f/tot;
  if (tid < PP){
    float al = s_e[tid]*inv;
    s_e[tid] = al;
    alphas[(size_t)b*TSTEPS*PP + (size_t)t*PP + tid] = al;
  }
  __syncthreads();
  // awe: each thread handles half2 columns tid and tid+512
  const __half2* eb = (const __half2*)g_ench + (size_t)b*PP*(ENC/2);
  float ax=0.f, ay=0.f, cx=0.f, cy=0.f;
  #pragma unroll 2
  for (int p=0;p<PP;p++){
    float al = s_e[p];
    float2 f0 = __half22float2(eb[(size_t)p*(ENC/2) + tid]);
    float2 f1 = __half22float2(eb[(size_t)p*(ENC/2) + tid + 512]);
    ax += al*f0.x; ay += al*f0.y;
    cx += al*f1.x; cy += al*f1.y;
  }
  int e = tid*2;
  float g0 = sigmoidf_(g_gatepre[b*ENC+e]   + b_beta[e]);
  float g1 = sigmoidf_(g_gatepre[b*ENC+e+1] + b_beta[e+1]);
  *(float2*)(g_xe + (size_t)b*ENC + e) = make_float2(g0*ax, g1*ay);
  int e2 = e + 1024;
  float g2 = sigmoidf_(g_gatepre[b*ENC+e2]   + b_beta[e2]);
  float g3 = sigmoidf_(g_gatepre[b*ENC+e2+1] + b_beta[e2+1]);
  *(float2*)(g_xe + (size_t)b*ENC + e2) = make_float2(g2*cx, g3*cy);
}

// per-step: split-K partials of xe @ W_ih[:, 512:]^T (fp32, K=2048)
__global__ void __launch_bounds__(256) k_gates(const float* __restrict__ Wih, int t){
  __shared__ __align__(16) float sbuf[32*68 + 32*132];
  float* sA = sbuf;
  float* sW = sbuf + 32*68;
  int tid=threadIdx.x, tx=tid&15, ty=tid>>4;
  int gn0 = blockIdx.x*128;
  int kx = blockIdx.z*KSLICE;          // into g_xe row [0,2048)
  int kw = EMB + kx;                   // into W_ih row [512,2560)
  int nact = g_bact[t];
  bool act = (ty*4 < nact);
  int rA0 = tid>>3,        kqA0 = tid&7;
  int rA1 = (tid+256)>>3,  kqA1 = (tid+256)&7;
  const float* ApA0 = g_xe + (size_t)rA0*ENC + kx + kqA0*4;
  const float* ApA1 = g_xe + (size_t)rA1*ENC + kx + kqA1*4;
  int rW = tid>>3, kqW = tid&7;
  const float* Wp = Wih + (size_t)gn0*XDIM + kw;
  float4 pa0=*(const float4*)ApA0, pa1=*(const float4*)ApA1;
  float4 pw[4];
  #pragma unroll
  for (int i=0;i<4;i++) pw[i] = *(const float4*)(Wp + (size_t)(rW + i*32)*XDIM + kqW*4);
  float acc[4][8]={};
  for (int k0=0;k0<KSLICE;k0+=32){
    sA[(kqA0*4+0)*68+rA0]=pa0.x; sA[(kqA0*4+1)*68+rA0]=pa0.y; sA[(kqA0*4+2)*68+rA0]=pa0.z; sA[(kqA0*4+3)*68+rA0]=pa0.w;
    sA[(kqA1*4+0)*68+rA1]=pa1.x; sA[(kqA1*4+1)*68+rA1]=pa1.y; sA[(kqA1*4+2)*68+rA1]=pa1.z; sA[(kqA1*4+3)*68+rA1]=pa1.w;
    #pragma unroll
    for (int i=0;i<4;i++){
      int n = rW + i*32;
      sW[(kqW*4+0)*132+n]=pw[i].x; sW[(kqW*4+1)*132+n]=pw[i].y; sW[(kqW*4+2)*132+n]=pw[i].z; sW[(kqW*4+3)*132+n]=pw[i].w;
    }
    __syncthreads();
    if (k0+32<KSLICE){
      pa0=*(const float4*)(ApA0+k0+32); pa1=*(const float4*)(ApA1+k0+32);
      #pragma unroll
      for (int i=0;i<4;i++) pw[i] = *(const float4*)(Wp + (size_t)(rW + i*32)*XDIM + kqW*4 + k0+32);
    }
    if (act){
      #pragma unroll
      for (int k=0;k<32;k++){
        float4 a=*(const float4*)&sA[k*68+ty*4];
        float4 ya=*(const float4*)&sW[k*132+tx*8];
        float4 yb=*(const float4*)&sW[k*132+tx*8+4];
        float av[4]={a.x,a.y,a.z,a.w};
        float wv[8]={ya.x,ya.y,ya.z,ya.w,yb.x,yb.y,yb.z,yb.w};
        #pragma unroll
        for (int i=0;i<4;i++)
          #pragma unroll
          for (int j=0;j<8;j++)
            acc[i][j] += av[i]*wv[j];
      }
    }
    __syncthreads();
  }
  if (act){
    float* outp = g_gpart + (size_t)blockIdx.z*B*G4;
    #pragma unroll
    for (int i=0;i<4;i++){
      int mm = ty*4+i;
      if (mm < nact){
        *(float4*)(outp + (size_t)mm*G4 + gn0 + tx*8)     = make_float4(acc[i][0],acc[i][1],acc[i][2],acc[i][3]);
        *(float4*)(outp + (size_t)mm*G4 + gn0 + tx*8 + 4) = make_float4(acc[i][4],acc[i][5],acc[i][6],acc[i][7]);
      }
    }
  }
}

// per-step LSTM pointwise (adds precomputed emb contribution)
__global__ void k_lstm(const float* __restrict__ b_ih, const float* __restrict__ b_hh, int t){
  int b = blockIdx.x;
  if (b >= g_bact[t]) return;
  int j = threadIdx.x;
  const size_t S = (size_t)B*G4;
  int base = b*G4;
  const float* eg = g_eg + ((size_t)b*TSTEPS + t)*G4;
  float g[4];
  #pragma unroll
  for (int q=0;q<4;q++){
    int off = base + q*DEC + j;
    float v = g_gates[off] + eg[q*DEC+j] + b_ih[q*DEC+j] + b_hh[q*DEC+j];
    #pragma unroll
    for (int s=0;s<NSLICE;s++) v += g_gpart[(size_t)s*S + off];
    g[q] = v;
  }
  float cn = sigmoidf_(g[1])*g_c[b*DEC+j] + sigmoidf_(g[0])*tanhf(g[2]);
  float hn = sigmoidf_(g[3])*tanhf(cn);
  g_c[b*DEC+j]=cn; g_h[b*DEC+j]=hn;
}

// ---------------- launch ----------------
extern "C" void kernel_launch(void* const* d_in, const int* in_sizes, int n_in,
                              void* d_out, int out_size){
  (void)in_sizes; (void)n_in; (void)out_size;
  const float* enc       = (const float*)d_in[0];
  const int*   caps      = (const int*)  d_in[1];
  const int*   caplen    = (const int*)  d_in[2];
  const float* emb_table = (const float*)d_in[3];
  const float* W_enc_att = (const float*)d_in[4];
  const float* b_enc_att = (const float*)d_in[5];
  const float* W_dec_att = (const float*)d_in[6];
  const float* b_dec_att = (const float*)d_in[7];
  const float* w_full    = (const float*)d_in[8];
  const float* b_full    = (const float*)d_in[9];
  const float* W_init_h  = (const float*)d_in[10];
  const float* b_init_h  = (const float*)d_in[11];
  const float* W_init_c  = (const float*)d_in[12];
  const float* b_init_c  = (const float*)d_in[13];
  const float* W_beta    = (const float*)d_in[14];
  const float* b_beta    = (const float*)d_in[15];
  const float* W_ih      = (const float*)d_in[16];
  const float* b_ih      = (const float*)d_in[17];
  const float* W_hh      = (const float*)d_in[18];
  const float* b_hh      = (const float*)d_in[19];
  const float* fc_W      = (const float*)d_in[20];
  const float* fc_b      = (const float*)d_in[21];

  float* preds  = (float*)d_out;                       // [B, T, V]
  float* alphas = preds + (size_t)B*TSTEPS*V;          // [B, T, P]

  k_bact<<<1, 32>>>(caplen);
  k_cvtmean<<<dim3(B, ENC/256), 256>>>(enc);
  k_cvtfcw<<<(int)(((size_t)V*DEC/4 + 255)/256), 256>>>(fc_W);
  k_init<<<dim3(32,1,4), 256>>>(W_init_h, W_init_c);
  k_init_red<<<64, 256>>>(b_init_h, b_init_c);
  k_att1_tc<<<dim3(ATT/128, (B*PP)/64), 256>>>(enc, W_enc_att, b_enc_att);
  k_embgate<<<dim3(G4/128, (B*TSTEPS)/64), 256>>>(emb_table, caps, W_ih);

  for (int t=0; t<TSTEPS; t++){
    if (t == 0)
      k_hproj_only<<<HPBLK, 256>>>(W_dec_att, W_beta, W_hh, t);
    else
      k_fc_hproj<<<FCBLK+HPBLK, 256>>>(fc_b, preds, W_dec_att, W_beta, W_hh, t);
    k_alpha_awe<<<B, 512>>>(b_dec_att, w_full, b_full, b_beta, alphas, t);
    k_gates<<<dim3(G4/128, 1, NSLICE), 256>>>(W_ih, t);
    k_lstm <<<B, DEC>>>(b_ih, b_hh, t);
  }
  k_fc_only<<<FCBLK, 256>>>(fc_b, preds, TSTEPS-1);
}